// round 8
// baseline (speedup 1.0000x reference)
#include <cuda_runtime.h>
#include <cuda_bf16.h>
#include <cuda_fp16.h>
#include <cstdint>

#define XDIM 512
#define YDIM 512
#define NPIX (XDIM*YDIM)      // 262144
#define VNUM 150000
#define HID 64
#define CO 256
#define KEFF 2304             // 9 taps * 256 ch (single fp16 slot)
#define KROW 256              // per-pixel slots

// ---------------- scratch ----------------
__device__ __align__(256) float g_pool[(VNUM + 32)*HID];       // pooled pillar feats
__device__ __align__(256) float g_buf1[(size_t)NPIX*CO];
__device__ __align__(256) float g_buf2[(size_t)NPIX*CO];
__device__ __align__(256) __half g_a3a[(size_t)NPIX*KROW];
__device__ __align__(256) __half g_a3b[(size_t)NPIX*KROW];
__device__ __align__(256) float g_wt1[HID*CO];
__device__ __align__(256) __half g_bA[(size_t)CO*KEFF];
__device__ __align__(256) __half g_bB[(size_t)CO*KEFF];
__device__ __align__(256) float g_stats[4*CO];
__device__ __align__(256) float g_bn[4*CO];

__device__ __forceinline__ uint32_t smem_u32(const void* p) {
    uint32_t a;
    asm("{ .reg .u64 t; cvta.to.shared.u64 t, %1; cvt.u32.u64 %0, t; }" : "=r"(a) : "l"(p));
    return a;
}

#define LDSM_X4(r0,r1,r2,r3,addr) \
    asm volatile("ldmatrix.sync.aligned.m8n8.x4.shared.b16 {%0,%1,%2,%3}, [%4];" \
        : "=r"(r0),"=r"(r1),"=r"(r2),"=r"(r3) : "r"(addr))
#define MMA_F16(d, a, b) \
    asm volatile("mma.sync.aligned.m16n8k16.row.col.f32.f16.f16.f32 " \
        "{%0,%1,%2,%3},{%4,%5,%6,%7},{%8,%9},{%0,%1,%2,%3};" \
        : "+f"((d)[0]),"+f"((d)[1]),"+f"((d)[2]),"+f"((d)[3]) \
        : "r"((a)[0]),"r"((a)[1]),"r"((a)[2]),"r"((a)[3]),"r"((b)[0]),"r"((b)[1]))
#define CP_ASYNC(dst, src, sz) \
    asm volatile("cp.async.cg.shared.global [%0], [%1], 16, %2;" \
        :: "r"(dst), "l"(src), "r"(sz))
#define CP_COMMIT() asm volatile("cp.async.commit_group;")
#define CP_WAIT1()  asm volatile("cp.async.wait_group 1;")
#define CP_WAIT0()  asm volatile("cp.async.wait_group 0;")

// ---------------- zero stats ----------------
__global__ void zero_stats() {
    for (int i = threadIdx.x; i < 4*CO; i += blockDim.x) g_stats[i] = 0.f;
}

// ---------------- init a3a = fp16(conv1 bias) everywhere ----------------
__global__ void init_a3(const float* __restrict__ bias, __half* __restrict__ a3) {
    __shared__ __half hb[256];
    if (threadIdx.x < 256) hb[threadIdx.x] = __float2half_rn(bias[threadIdx.x]);
    __syncthreads();
    uint4* dst = (uint4*)a3;
    const uint4* src = (const uint4*)hb;   // 32 uint4 per channel period
    const int total = NPIX*256/8;          // uint4 count
    for (int i = blockIdx.x*blockDim.x + threadIdx.x; i < total; i += gridDim.x*blockDim.x)
        dst[i] = src[i & 31];
}

// ---------------- weight prep: conv1 transpose + fp16 B for convA/B ----------
__global__ void prep_weights(const float* __restrict__ c1w,
                             const float* __restrict__ cAw,
                             const float* __restrict__ cBw) {
    const int total1 = HID*CO;
    const int totalc = CO*CO*9;
    for (int i = blockIdx.x*blockDim.x + threadIdx.x; i < total1 + 2*totalc;
         i += gridDim.x*blockDim.x) {
        if (i < total1) {
            int o = i & 255, c = i >> 8;
            g_wt1[i] = c1w[o*HID + c];
        } else {
            int j = i - total1;
            const float* src = cAw; __half* dst = g_bA;
            if (j >= totalc) { j -= totalc; src = cBw; dst = g_bB; }
            int o = j / 2304, k = j % 2304;
            int c = k / 9, tap = k % 9;
            float w = src[(size_t)o*2304 + c*9 + tap];
            dst[(size_t)o*KEFF + tap*KROW + c] = __float2half_rn(w);
        }
    }
}

// ---------------- pillar MLP + pool (compact output) ----------------
__global__ void __launch_bounds__(128) pillar_mlp(
    const float* __restrict__ pillars, const int* __restrict__ nump,
    const float* __restrict__ w1, const float* __restrict__ b1,
    const float* __restrict__ w2, const float* __restrict__ b2)
{
    __shared__ __align__(16) float w2q[64*64];
    __shared__ __align__(16) float h1s[2][32*64];
    __shared__ __align__(16) float pts[2][128];
    const int tid = threadIdx.x;
    const int g = tid >> 6, t = tid & 63;
    const int v = blockIdx.x*2 + g;

    for (int i = tid; i < 4096; i += 128) {
        int tt = i >> 6, j = i & 63;
        w2q[((j>>2)*64 + tt)*4 + (j&3)] = w2[i];
    }
    float4 w1r = *(const float4*)(w1 + t*4);
    float b1t = b1[t], b2t = b2[t];

    if (v < VNUM) {
        float mask = (nump[v] > 0) ? 1.f : 0.f;
        pts[g][t]      = pillars[(size_t)v*128 + t] * mask;
        pts[g][t + 64] = pillars[(size_t)v*128 + 64 + t] * mask;
    } else { pts[g][t] = 0.f; pts[g][t + 64] = 0.f; }
    __syncthreads();

    #pragma unroll
    for (int p = 0; p < 32; p++) {
        float4 xp = *(float4*)&pts[g][p*4];
        float h = fmaf(w1r.x, xp.x, fmaf(w1r.y, xp.y, fmaf(w1r.z, xp.z, fmaf(w1r.w, xp.w, b1t))));
        h1s[g][p*64 + t] = fmaxf(h, 0.f);
    }
    __syncthreads();

    float acc = 0.f;
    #pragma unroll
    for (int po = 0; po < 4; po++) {
        float s[8];
        #pragma unroll
        for (int pp = 0; pp < 8; pp++) s[pp] = b2t;
        #pragma unroll
        for (int jq = 0; jq < 16; jq++) {
            float4 w = *(float4*)&w2q[(jq*64 + t)*4];
            #pragma unroll
            for (int pp = 0; pp < 8; pp++) {
                float4 hh = *(float4*)&h1s[g][(po*8 + pp)*64 + jq*4];
                s[pp] = fmaf(w.x, hh.x, s[pp]); s[pp] = fmaf(w.y, hh.y, s[pp]);
                s[pp] = fmaf(w.z, hh.z, s[pp]); s[pp] = fmaf(w.w, hh.w, s[pp]);
            }
        }
        #pragma unroll
        for (int pp = 0; pp < 8; pp++) acc += fmaxf(s[pp], 0.f);
    }
    if (v < VNUM) g_pool[(size_t)v*HID + t] = acc * (1.f/32.f);
}

// ---------------- conv1 on compact pillars + scatter to a3a ----------------
// block = 256 threads (thread = out channel), 32 pillars per block
__global__ void __launch_bounds__(256) conv1_scatter(
    const int* __restrict__ indices, const float* __restrict__ bias,
    __half* __restrict__ a3)
{
    __shared__ __align__(16) float xs[32][65];
    __shared__ int sxy[32];
    const int tid = threadIdx.x;
    const int v0 = blockIdx.x * 32;

    if (tid < 32) {
        int v = v0 + tid, xy = -1;
        if (v < VNUM) {
            int xv = indices[2*v], yv = indices[2*v + 1];
            if ((unsigned)xv < XDIM && (unsigned)yv < YDIM) xy = xv*YDIM + yv;
        }
        sxy[tid] = xy;
    }
    for (int i = tid; i < 2048; i += 256) {
        int p = i >> 6, c = i & 63;
        int v = v0 + p;
        xs[p][c] = (v < VNUM) ? g_pool[(size_t)v*HID + c] : 0.f;
    }
    __syncthreads();

    float w[64];
    #pragma unroll
    for (int c = 0; c < 64; c++) w[c] = g_wt1[c*CO + tid];
    const float b = bias[tid];

    #pragma unroll 4
    for (int p = 0; p < 32; p++) {
        int xy = sxy[p];
        if (xy < 0) continue;
        float acc = b;
        #pragma unroll
        for (int c = 0; c < 64; c++) acc = fmaf(w[c], xs[p][c], acc);
        a3[(size_t)xy*KROW + tid] = __float2half_rn(acc);
    }
}

// ---------------- mma.sync 3x3 conv: 128 pix x 128 oc tile, K=2304 ----------
// 8 warps (2M x 4N), warp tile 64x32, 36 chunks of 64 K
// 3-stage cp.async pipeline, ONE __syncthreads per iteration
// smem: 3 stages x (A 16K + B 16K) = 96K, bias at 98304
__global__ void __launch_bounds__(256, 2) conv_mma(
    const __half* __restrict__ a3w, const __half* __restrict__ b3w,
    const float* __restrict__ bias, float* __restrict__ out,
    float* __restrict__ sumb, float* __restrict__ sqb)
{
    extern __shared__ char sm[];
    const char* a3 = (const char*)a3w;
    const char* b3 = (const char*)b3w;
    const int tid = threadIdx.x, wid = tid >> 5, lane = tid & 31;
    const int wm = wid >> 2, wn = wid & 3;
    const uint32_t sb = smem_u32(sm);
    float* sbias = (float*)(sm + 98304);

    const int xr = blockIdx.x >> 2;               // x-row 0..511
    const int y0 = (blockIdx.x & 3) * 128;        // y base
    const int p0 = xr*512 + y0;
    const int o0 = blockIdx.y * 128;

    sbias[tid] = bias[tid];

    const int a_row = wm*64 + (lane & 15);
    const int a_kb  = (lane >> 4) * 16;
    const int b_row = wn*32 + ((lane & 16) >> 1) + (lane & 7);
    const int b_kb  = (lane & 8) ? 16 : 0;

    const int l_row = tid >> 3;        // 0..31, +32 per i
    const int l_j   = (tid & 7) * 16;  // byte col

    float acc[4][4][4];
    #pragma unroll
    for (int i = 0; i < 4; i++)
        #pragma unroll
        for (int j = 0; j < 4; j++)
            #pragma unroll
            for (int k = 0; k < 4; k++) acc[i][j][k] = 0.f;

    auto load_chunk = [&](int c, int slot) {
        const int tap = c >> 2, kc = c & 3;
        const int dx = tap/3 - 1, dyy = tap - (tap/3)*3 - 1;
        const int xx = xr + dx;
        const bool xok = (unsigned)xx < XDIM;
        const uint32_t abase = sb + slot*32768u;
        const uint32_t bbase = abase + 16384u;
        #pragma unroll
        for (int i = 0; i < 4; i++) {
            int row = l_row + i*32;
            int yy = y0 + row + dyy;
            bool ok = xok && ((unsigned)yy < YDIM);
            const char* src = ok ? (a3 + ((size_t)(xx*512 + yy))*512 + kc*128 + l_j)
                                 : a3;
            uint32_t off = row*128 + l_j; off ^= (off >> 3) & 0x70;
            CP_ASYNC(abase + off, src, ok ? 16 : 0);
        }
        #pragma unroll
        for (int i = 0; i < 4; i++) {
            int row = l_row + i*32;
            const char* src = b3 + (size_t)(o0 + row)*4608 + tap*512 + kc*128 + l_j;
            uint32_t off = row*128 + l_j; off ^= (off >> 3) & 0x70;
            CP_ASYNC(bbase + off, src, 16);
        }
    };

    load_chunk(0, 0); CP_COMMIT();
    load_chunk(1, 1); CP_COMMIT();

    for (int c = 0; c < 36; c++) {
        if (c < 35) CP_WAIT1(); else CP_WAIT0();
        __syncthreads();   // chunk c visible to all; all warps done with c-1
        if (c + 2 < 36) { load_chunk(c + 2, (c + 2) % 3); CP_COMMIT(); }

        const uint32_t sa  = sb + (uint32_t)(c % 3)*32768u;
        const uint32_t sbm = sa + 16384u;
        #pragma unroll
        for (int ks = 0; ks < 4; ks++) {
            uint32_t af[4][4], bf[4][2];
            #pragma unroll
            for (int mt = 0; mt < 4; mt++) {
                uint32_t off = (a_row + mt*16)*128 + a_kb + ks*32;
                off ^= (off >> 3) & 0x70;
                LDSM_X4(af[mt][0], af[mt][1], af[mt][2], af[mt][3], sa + off);
            }
            #pragma unroll
            for (int pr = 0; pr < 2; pr++) {
                uint32_t off = (b_row + pr*16)*128 + b_kb + ks*32;
                off ^= (off >> 3) & 0x70;
                LDSM_X4(bf[pr*2][0], bf[pr*2][1], bf[pr*2+1][0], bf[pr*2+1][1], sbm + off);
            }
            #pragma unroll
            for (int mt = 0; mt < 4; mt++)
                #pragma unroll
                for (int nt = 0; nt < 4; nt++)
                    MMA_F16(acc[mt][nt], af[mt], bf[nt]);
        }
    }

    // epilogue: bias add, HWC store, BN stats
    #pragma unroll
    for (int nt = 0; nt < 4; nt++) {
        const int col = o0 + wn*32 + nt*8 + (lane & 3)*2;
        const float bs0 = sbias[col];
        const float bs1 = sbias[col + 1];
        float s0 = 0.f, q0 = 0.f, s1 = 0.f, q1 = 0.f;
        #pragma unroll
        for (int mt = 0; mt < 4; mt++) {
            const int prow = p0 + wm*64 + mt*16 + (lane >> 2);
            float v00 = acc[mt][nt][0] + bs0;
            float v01 = acc[mt][nt][1] + bs1;
            float v10 = acc[mt][nt][2] + bs0;
            float v11 = acc[mt][nt][3] + bs1;
            *(float2*)(out + (size_t)prow*CO + col)     = make_float2(v00, v01);
            *(float2*)(out + (size_t)(prow+8)*CO + col) = make_float2(v10, v11);
            s0 += v00 + v10; q0 += v00*v00 + v10*v10;
            s1 += v01 + v11; q1 += v01*v01 + v11*v11;
        }
        #pragma unroll
        for (int o = 4; o < 32; o <<= 1) {
            s0 += __shfl_xor_sync(0xffffffffu, s0, o);
            q0 += __shfl_xor_sync(0xffffffffu, q0, o);
            s1 += __shfl_xor_sync(0xffffffffu, s1, o);
            q1 += __shfl_xor_sync(0xffffffffu, q1, o);
        }
        if (lane < 4) {
            atomicAdd(sumb + col, s0); atomicAdd(sqb + col, q0);
            atomicAdd(sumb + col + 1, s1); atomicAdd(sqb + col + 1, q1);
        }
    }
}

// ---------------- BN finalize ----------------
__global__ void bn_finalize(const float* __restrict__ gamma,
                            const float* __restrict__ beta, int which) {
    int c = threadIdx.x;
    const float inv_n = 1.f / (float)NPIX;
    float mean = g_stats[which*512 + c] * inv_n;
    float var  = g_stats[which*512 + 256 + c] * inv_n - mean*mean;
    float sc = gamma[c] * rsqrtf(var + 1e-5f);
    g_bn[which*512 + c] = sc;
    g_bn[which*512 + 256 + c] = fmaf(-mean, sc, beta[c]);
}

// ---------------- BN-A apply + relu + fp16 convert ----------------
__global__ void bn_convert(const float* __restrict__ in, __half* __restrict__ a3) {
    __shared__ float sc[256], sh[256];
    if (threadIdx.x < 256) {
        sc[threadIdx.x] = g_bn[threadIdx.x];
        sh[threadIdx.x] = g_bn[256 + threadIdx.x];
    }
    __syncthreads();
    const float4* in4 = (const float4*)in;
    const int total4 = NPIX * 64;
    for (int i = blockIdx.x*blockDim.x + threadIdx.x; i < total4; i += gridDim.x*blockDim.x) {
        float4 v = in4[i];
        int c = (i & 63) * 4;
        size_t pix = (size_t)(i >> 6);
        float f[4] = {v.x, v.y, v.z, v.w};
        __half h[4];
        #pragma unroll
        for (int cc = 0; cc < 4; cc++)
            h[cc] = __float2half_rn(fmaxf(fmaf(f[cc], sc[c+cc], sh[c+cc]), 0.f));
        uint2 pk = make_uint2(
            ((uint32_t)__half_as_ushort(h[0])) | ((uint32_t)__half_as_ushort(h[1]) << 16),
            ((uint32_t)__half_as_ushort(h[2])) | ((uint32_t)__half_as_ushort(h[3]) << 16));
        *(uint2*)(a3 + pix*KROW + c) = pk;
    }
}

// ---------------- BN-B apply + relu + HWC->NCHW ----------------
__global__ void __launch_bounds__(256) bn_apply_nchw(const float* __restrict__ in,
                                                     float* __restrict__ out) {
    __shared__ float s[32*257];
    const int tid = threadIdx.x;
    const float sc = g_bn[512 + tid];
    const float sh = g_bn[768 + tid];
    const int xy0 = blockIdx.x * 32;
    #pragma unroll
    for (int m = 0; m < 32; m++) {
        float v = in[(size_t)(xy0 + m)*CO + tid];
        s[m*257 + tid] = fmaxf(fmaf(v, sc, sh), 0.f);
    }
    __syncthreads();
    #pragma unroll
    for (int m = 0; m < 32; m++) {
        int o = m*8 + (tid >> 5);
        int xyl = tid & 31;
        out[(size_t)o*NPIX + xy0 + xyl] = s[xyl*257 + o];
    }
}

// ---------------- launch ----------------
extern "C" void kernel_launch(void* const* d_in, const int* in_sizes, int n_in,
                              void* d_out, int out_size) {
    const float* pillars = (const float*)d_in[0];
    const int*   nump    = (const int*)d_in[1];
    const int*   indices = (const int*)d_in[2];
    const float* w1   = (const float*)d_in[3];
    const float* b1   = (const float*)d_in[4];
    const float* w2   = (const float*)d_in[5];
    const float* b2   = (const float*)d_in[6];
    const float* c1w  = (const float*)d_in[7];
    const float* c1b  = (const float*)d_in[8];
    const float* cAw  = (const float*)d_in[9];
    const float* cAb  = (const float*)d_in[10];
    const float* bnAg = (const float*)d_in[11];
    const float* bnAb = (const float*)d_in[12];
    const float* cBw  = (const float*)d_in[13];
    const float* cBb  = (const float*)d_in[14];
    const float* bnBg = (const float*)d_in[15];
    const float* bnBb = (const float*)d_in[16];
    float* out = (float*)d_out;

    float *p_buf1, *p_buf2, *p_stats;
    __half *p_a3a, *p_a3b, *p_bA, *p_bB;
    cudaGetSymbolAddress((void**)&p_buf1,  g_buf1);
    cudaGetSymbolAddress((void**)&p_buf2,  g_buf2);
    cudaGetSymbolAddress((void**)&p_stats, g_stats);
    cudaGetSymbolAddress((void**)&p_a3a,   g_a3a);
    cudaGetSymbolAddress((void**)&p_a3b,   g_a3b);
    cudaGetSymbolAddress((void**)&p_bA,    g_bA);
    cudaGetSymbolAddress((void**)&p_bB,    g_bB);

    static bool attr_done = false;
    if (!attr_done) {
        cudaFuncSetAttribute(conv_mma, cudaFuncAttributeMaxDynamicSharedMemorySize, 99328);
        attr_done = true;
    }

    zero_stats<<<1, 256>>>();
    prep_weights<<<1200, 256>>>(c1w, cAw, cBw);
    init_a3<<<2048, 256>>>(c1b, p_a3a);
    pillar_mlp<<<(VNUM + 1)/2, 128>>>(pillars, nump, w1, b1, w2, b2);
    conv1_scatter<<<(VNUM + 31)/32, 256>>>(indices, c1b, p_a3a);

    dim3 cgrid(2048, 2);
    conv_mma<<<cgrid, 256, 99328>>>(p_a3a, p_bA, cAb, p_buf1, p_stats, p_stats + 256);
    bn_finalize<<<1, 256>>>(bnAg, bnAb, 0);

    bn_convert<<<4096, 256>>>(p_buf1, p_a3b);

    conv_mma<<<cgrid, 256, 99328>>>(p_a3b, p_bB, cBb, p_buf2, p_stats + 512, p_stats + 768);
    bn_finalize<<<1, 256>>>(bnBg, bnBb, 1);

    bn_apply_nchw<<<NPIX/32, 256>>>(p_buf2, out);
}

// round 9
// speedup vs baseline: 1.5765x; 1.5765x over previous
#include <cuda_runtime.h>
#include <cuda_bf16.h>
#include <cuda_fp16.h>
#include <cstdint>

#define XDIM 512
#define YDIM 512
#define NPIX (XDIM*YDIM)      // 262144
#define VNUM 150000
#define HID 64
#define CO 256
#define KEFF 2304             // 9 taps * 256 ch (single fp16 slot)
#define KROW 256              // per-pixel slots

// ---------------- scratch ----------------
__device__ __align__(256) float g_buf1[(size_t)NPIX*CO];
__device__ __align__(256) float g_buf2[(size_t)NPIX*CO];
__device__ __align__(256) __half g_a3a[(size_t)NPIX*KROW];
__device__ __align__(256) __half g_a3b[(size_t)NPIX*KROW];
__device__ __align__(256) float g_wt1[HID*CO];          // conv1 W^T [c][o]
__device__ __align__(256) __half g_w2h[HID*HID];        // w2 fp16 [g][h]
__device__ __align__(256) __half g_bA[(size_t)CO*KEFF];
__device__ __align__(256) __half g_bB[(size_t)CO*KEFF];
__device__ __align__(256) float g_stats[4*CO];
__device__ __align__(256) float g_bn[4*CO];

__device__ __forceinline__ uint32_t smem_u32(const void* p) {
    uint32_t a;
    asm("{ .reg .u64 t; cvta.to.shared.u64 t, %1; cvt.u32.u64 %0, t; }" : "=r"(a) : "l"(p));
    return a;
}

#define LDSM_X4(r0,r1,r2,r3,addr) \
    asm volatile("ldmatrix.sync.aligned.m8n8.x4.shared.b16 {%0,%1,%2,%3}, [%4];" \
        : "=r"(r0),"=r"(r1),"=r"(r2),"=r"(r3) : "r"(addr))
#define MMA_F16(d, a, b) \
    asm volatile("mma.sync.aligned.m16n8k16.row.col.f32.f16.f16.f32 " \
        "{%0,%1,%2,%3},{%4,%5,%6,%7},{%8,%9},{%0,%1,%2,%3};" \
        : "+f"((d)[0]),"+f"((d)[1]),"+f"((d)[2]),"+f"((d)[3]) \
        : "r"((a)[0]),"r"((a)[1]),"r"((a)[2]),"r"((a)[3]),"r"((b)[0]),"r"((b)[1]))
#define CP_ASYNC(dst, src, sz) \
    asm volatile("cp.async.cg.shared.global [%0], [%1], 16, %2;" \
        :: "r"(dst), "l"(src), "r"(sz))
#define CP_COMMIT() asm volatile("cp.async.commit_group;")
#define CP_WAIT1()  asm volatile("cp.async.wait_group 1;")
#define CP_WAIT0()  asm volatile("cp.async.wait_group 0;")

// ---------------- zero stats ----------------
__global__ void zero_stats() {
    for (int i = threadIdx.x; i < 4*CO; i += blockDim.x) g_stats[i] = 0.f;
}

// ---------------- init a3a = fp16(conv1 bias) everywhere ----------------
__global__ void init_a3(const float* __restrict__ bias, __half* __restrict__ a3) {
    __shared__ __half hb[256];
    if (threadIdx.x < 256) hb[threadIdx.x] = __float2half_rn(bias[threadIdx.x]);
    __syncthreads();
    uint4* dst = (uint4*)a3;
    const uint4* src = (const uint4*)hb;
    const int total = NPIX*256/8;
    for (int i = blockIdx.x*blockDim.x + threadIdx.x; i < total; i += gridDim.x*blockDim.x)
        dst[i] = src[i & 31];
}

// ---------------- weight prep ----------------
__global__ void prep_weights(const float* __restrict__ c1w,
                             const float* __restrict__ w2,
                             const float* __restrict__ cAw,
                             const float* __restrict__ cBw) {
    const int total1 = HID*CO;        // 16384
    const int totalw2 = HID*HID;      // 4096
    const int totalc = CO*CO*9;       // 589824
    const int grand = total1 + totalw2 + 2*totalc;
    for (int i = blockIdx.x*blockDim.x + threadIdx.x; i < grand;
         i += gridDim.x*blockDim.x) {
        if (i < total1) {
            int o = i & 255, c = i >> 8;
            g_wt1[i] = c1w[o*HID + c];
        } else if (i < total1 + totalw2) {
            int j = i - total1;
            g_w2h[j] = __float2half_rn(w2[j]);
        } else {
            int j = i - total1 - totalw2;
            const float* src = cAw; __half* dst = g_bA;
            if (j >= totalc) { j -= totalc; src = cBw; dst = g_bB; }
            int o = j / 2304, k = j % 2304;
            int c = k / 9, tap = k % 9;
            float w = src[(size_t)o*2304 + c*9 + tap];
            dst[(size_t)o*KEFF + tap*KROW + c] = __float2half_rn(w);
        }
    }
}

// ---------------- fused pillar MLP (HMMA stage2) + pool + conv1 + scatter ----
// block = 256 threads (8 warps), 8 pillars/block, 18750 blocks
// smem layout (dynamic, 49152):
//   [0, 32768)      h1 fp16, 256 rows x 64 ch (128B rows, XOR-swizzled)
//   [32768, 40960)  w2 fp16, 64 rows x 64 k (swizzled)
//   [40960, 45056)  pts float4[256]
//   [45056, 47104)  pooled float[8][64]
//   [47104, 48128)  w1s float[256]
//   [48128, 48384)  b1s float[64]
//   [48384, 48640)  b2s float[64]
//   [48640, 48672)  maskf float[8]
//   [48672, 48704)  sxy int[8]
__global__ void __launch_bounds__(256, 2) pillar_fused(
    const float* __restrict__ pillars, const int* __restrict__ nump,
    const int* __restrict__ indices, const float* __restrict__ w1,
    const float* __restrict__ b1, const float* __restrict__ b2,
    const float* __restrict__ c1b, __half* __restrict__ a3)
{
    extern __shared__ char sm[];
    const int tid = threadIdx.x, lane = tid & 31, wid = tid >> 5;
    const uint32_t sb = smem_u32(sm);
    const int v0 = blockIdx.x * 8;

    float4* pts4   = (float4*)(sm + 40960);
    float*  pooled = (float*)(sm + 45056);
    float*  w1s    = (float*)(sm + 47104);
    float*  b1s    = (float*)(sm + 48128);
    float*  b2s    = (float*)(sm + 48384);
    float*  maskf  = (float*)(sm + 48640);
    int*    sxy    = (int*)(sm + 48672);

    w1s[tid] = w1[tid];                       // 64x4 = 256
    if (tid < 64) { b1s[tid] = b1[tid]; b2s[tid] = b2[tid]; }
    if (tid < 8) {
        int v = v0 + tid;
        maskf[tid] = (nump[v] > 0) ? 1.f : 0.f;
        int xv = indices[2*v], yv = indices[2*v + 1];
        sxy[tid] = ((unsigned)xv < XDIM && (unsigned)yv < YDIM) ? xv*YDIM + yv : -1;
    }
    pts4[tid] = *(const float4*)(pillars + (size_t)v0*128 + tid*4);
    {
        const uint4* w2g = (const uint4*)g_w2h;
        #pragma unroll
        for (int i = 0; i < 2; i++) {
            int idx = tid*2 + i;              // g = idx/8, grp = idx%8
            int g = idx >> 3, grp = idx & 7;
            uint32_t off = 32768u + (uint32_t)((g*128 + grp*16) ^ ((g & 7) << 4));
            *(uint4*)(sm + off) = w2g[idx];
        }
    }
    __syncthreads();

    // ---- stage A: h1 = relu(x @ w1^T + b1), fp16 to swizzled smem ----
    {
        float4 x = pts4[tid];
        float m = maskf[tid >> 5];
        x.x *= m; x.y *= m; x.z *= m; x.w *= m;
        const int phase = (tid >> 3) & 7;     // stagger to avoid bank conflicts
        #pragma unroll
        for (int g8 = 0; g8 < 8; g8++) {
            int grp = (g8 + phase) & 7;
            uint32_t pk[4];
            #pragma unroll
            for (int u = 0; u < 4; u++) {
                int t0 = grp*8 + u*2;
                float4 wa = *(float4*)&w1s[t0*4];
                float4 wb = *(float4*)&w1s[t0*4 + 4];
                float h0 = fmaf(wa.x, x.x, fmaf(wa.y, x.y, fmaf(wa.z, x.z, fmaf(wa.w, x.w, b1s[t0]))));
                float h1v = fmaf(wb.x, x.x, fmaf(wb.y, x.y, fmaf(wb.z, x.z, fmaf(wb.w, x.w, b1s[t0+1]))));
                __half2 hh = __floats2half2_rn(fmaxf(h0, 0.f), fmaxf(h1v, 0.f));
                pk[u] = *(uint32_t*)&hh;
            }
            uint32_t off = (uint32_t)((tid*128 + grp*16) ^ ((tid & 7) << 4));
            *(uint4*)(sm + off) = make_uint4(pk[0], pk[1], pk[2], pk[3]);
        }
    }
    __syncthreads();

    // ---- stage B: per-warp pillar GEMM h1[32x64] @ w2^T[64x64], bias+relu+pool
    const int a_row = wid*32 + (lane & 15);
    const int a_kb  = (lane >> 4) * 16;
    const int b_row = ((lane & 16) >> 1) + (lane & 7);
    const int b_kb  = (lane & 8) ? 16 : 0;

    float acc[2][8][4];
    #pragma unroll
    for (int i = 0; i < 2; i++)
        #pragma unroll
        for (int j = 0; j < 8; j++)
            #pragma unroll
            for (int k = 0; k < 4; k++) acc[i][j][k] = 0.f;

    #pragma unroll
    for (int ks = 0; ks < 4; ks++) {
        uint32_t af[2][4], bf[8][2];
        #pragma unroll
        for (int mt = 0; mt < 2; mt++) {
            uint32_t off = (a_row + mt*16)*128 + a_kb + ks*32;
            off ^= (off >> 3) & 0x70;
            LDSM_X4(af[mt][0], af[mt][1], af[mt][2], af[mt][3], sb + off);
        }
        #pragma unroll
        for (int pr = 0; pr < 4; pr++) {
            uint32_t off = (b_row + pr*16)*128 + b_kb + ks*32;
            off ^= (off >> 3) & 0x70;
            LDSM_X4(bf[pr*2][0], bf[pr*2][1], bf[pr*2+1][0], bf[pr*2+1][1], sb + 32768u + off);
        }
        #pragma unroll
        for (int mt = 0; mt < 2; mt++)
            #pragma unroll
            for (int nt = 0; nt < 8; nt++)
                MMA_F16(acc[mt][nt], af[mt], bf[nt]);
    }

    #pragma unroll
    for (int nt = 0; nt < 8; nt++) {
        const int col = nt*8 + (lane & 3)*2;
        const float bb0 = b2s[col], bb1 = b2s[col + 1];
        float s0 = fmaxf(acc[0][nt][0] + bb0, 0.f) + fmaxf(acc[0][nt][2] + bb0, 0.f)
                 + fmaxf(acc[1][nt][0] + bb0, 0.f) + fmaxf(acc[1][nt][2] + bb0, 0.f);
        float s1 = fmaxf(acc[0][nt][1] + bb1, 0.f) + fmaxf(acc[0][nt][3] + bb1, 0.f)
                 + fmaxf(acc[1][nt][1] + bb1, 0.f) + fmaxf(acc[1][nt][3] + bb1, 0.f);
        #pragma unroll
        for (int o = 4; o < 32; o <<= 1) {
            s0 += __shfl_xor_sync(0xffffffffu, s0, o);
            s1 += __shfl_xor_sync(0xffffffffu, s1, o);
        }
        if (lane < 4) {
            pooled[wid*64 + col]     = s0 * (1.f/32.f);
            pooled[wid*64 + col + 1] = s1 * (1.f/32.f);
        }
    }
    __syncthreads();

    // ---- stage C: conv1 (pooled[8][64] @ w1t[64][256]) + scatter fp16 ----
    float wv[64];
    #pragma unroll
    for (int c = 0; c < 64; c++) wv[c] = g_wt1[c*CO + tid];
    float accp[8];
    const float bo = c1b[tid];
    #pragma unroll
    for (int p = 0; p < 8; p++) accp[p] = bo;
    const float4* pool4 = (const float4*)pooled;
    #pragma unroll
    for (int c4 = 0; c4 < 16; c4++) {
        #pragma unroll
        for (int p = 0; p < 8; p++) {
            float4 pv = pool4[p*16 + c4];
            accp[p] = fmaf(wv[c4*4],   pv.x, accp[p]);
            accp[p] = fmaf(wv[c4*4+1], pv.y, accp[p]);
            accp[p] = fmaf(wv[c4*4+2], pv.z, accp[p]);
            accp[p] = fmaf(wv[c4*4+3], pv.w, accp[p]);
        }
    }
    #pragma unroll
    for (int p = 0; p < 8; p++) {
        int xy = sxy[p];
        if (xy >= 0) a3[(size_t)xy*KROW + tid] = __float2half_rn(accp[p]);
    }
}

// ---------------- mma.sync 3x3 conv (unchanged from R8) ----------------
__global__ void __launch_bounds__(256, 2) conv_mma(
    const __half* __restrict__ a3w, const __half* __restrict__ b3w,
    const float* __restrict__ bias, float* __restrict__ out,
    float* __restrict__ sumb, float* __restrict__ sqb)
{
    extern __shared__ char sm[];
    const char* a3 = (const char*)a3w;
    const char* b3 = (const char*)b3w;
    const int tid = threadIdx.x, wid = tid >> 5, lane = tid & 31;
    const int wm = wid >> 2, wn = wid & 3;
    const uint32_t sb = smem_u32(sm);
    float* sbias = (float*)(sm + 98304);

    const int xr = blockIdx.x >> 2;
    const int y0 = (blockIdx.x & 3) * 128;
    const int p0 = xr*512 + y0;
    const int o0 = blockIdx.y * 128;

    sbias[tid] = bias[tid];

    const int a_row = wm*64 + (lane & 15);
    const int a_kb  = (lane >> 4) * 16;
    const int b_row = wn*32 + ((lane & 16) >> 1) + (lane & 7);
    const int b_kb  = (lane & 8) ? 16 : 0;

    const int l_row = tid >> 3;
    const int l_j   = (tid & 7) * 16;

    float acc[4][4][4];
    #pragma unroll
    for (int i = 0; i < 4; i++)
        #pragma unroll
        for (int j = 0; j < 4; j++)
            #pragma unroll
            for (int k = 0; k < 4; k++) acc[i][j][k] = 0.f;

    auto load_chunk = [&](int c, int slot) {
        const int tap = c >> 2, kc = c & 3;
        const int dx = tap/3 - 1, dyy = tap - (tap/3)*3 - 1;
        const int xx = xr + dx;
        const bool xok = (unsigned)xx < XDIM;
        const uint32_t abase = sb + slot*32768u;
        const uint32_t bbase = abase + 16384u;
        #pragma unroll
        for (int i = 0; i < 4; i++) {
            int row = l_row + i*32;
            int yy = y0 + row + dyy;
            bool ok = xok && ((unsigned)yy < YDIM);
            const char* src = ok ? (a3 + ((size_t)(xx*512 + yy))*512 + kc*128 + l_j)
                                 : a3;
            uint32_t off = row*128 + l_j; off ^= (off >> 3) & 0x70;
            CP_ASYNC(abase + off, src, ok ? 16 : 0);
        }
        #pragma unroll
        for (int i = 0; i < 4; i++) {
            int row = l_row + i*32;
            const char* src = b3 + (size_t)(o0 + row)*4608 + tap*512 + kc*128 + l_j;
            uint32_t off = row*128 + l_j; off ^= (off >> 3) & 0x70;
            CP_ASYNC(bbase + off, src, 16);
        }
    };

    load_chunk(0, 0); CP_COMMIT();
    load_chunk(1, 1); CP_COMMIT();

    for (int c = 0; c < 36; c++) {
        if (c < 35) CP_WAIT1(); else CP_WAIT0();
        __syncthreads();
        if (c + 2 < 36) { load_chunk(c + 2, (c + 2) % 3); CP_COMMIT(); }

        const uint32_t sa  = sb + (uint32_t)(c % 3)*32768u;
        const uint32_t sbm = sa + 16384u;
        #pragma unroll
        for (int ks = 0; ks < 4; ks++) {
            uint32_t af[4][4], bf[4][2];
            #pragma unroll
            for (int mt = 0; mt < 4; mt++) {
                uint32_t off = (a_row + mt*16)*128 + a_kb + ks*32;
                off ^= (off >> 3) & 0x70;
                LDSM_X4(af[mt][0], af[mt][1], af[mt][2], af[mt][3], sa + off);
            }
            #pragma unroll
            for (int pr = 0; pr < 2; pr++) {
                uint32_t off = (b_row + pr*16)*128 + b_kb + ks*32;
                off ^= (off >> 3) & 0x70;
                LDSM_X4(bf[pr*2][0], bf[pr*2][1], bf[pr*2+1][0], bf[pr*2+1][1], sbm + off);
            }
            #pragma unroll
            for (int mt = 0; mt < 4; mt++)
                #pragma unroll
                for (int nt = 0; nt < 4; nt++)
                    MMA_F16(acc[mt][nt], af[mt], bf[nt]);
        }
    }

    #pragma unroll
    for (int nt = 0; nt < 4; nt++) {
        const int col = o0 + wn*32 + nt*8 + (lane & 3)*2;
        const float bs0 = sbias[col];
        const float bs1 = sbias[col + 1];
        float s0 = 0.f, q0 = 0.f, s1 = 0.f, q1 = 0.f;
        #pragma unroll
        for (int mt = 0; mt < 4; mt++) {
            const int prow = p0 + wm*64 + mt*16 + (lane >> 2);
            float v00 = acc[mt][nt][0] + bs0;
            float v01 = acc[mt][nt][1] + bs1;
            float v10 = acc[mt][nt][2] + bs0;
            float v11 = acc[mt][nt][3] + bs1;
            *(float2*)(out + (size_t)prow*CO + col)     = make_float2(v00, v01);
            *(float2*)(out + (size_t)(prow+8)*CO + col) = make_float2(v10, v11);
            s0 += v00 + v10; q0 += v00*v00 + v10*v10;
            s1 += v01 + v11; q1 += v01*v01 + v11*v11;
        }
        #pragma unroll
        for (int o = 4; o < 32; o <<= 1) {
            s0 += __shfl_xor_sync(0xffffffffu, s0, o);
            q0 += __shfl_xor_sync(0xffffffffu, q0, o);
            s1 += __shfl_xor_sync(0xffffffffu, s1, o);
            q1 += __shfl_xor_sync(0xffffffffu, q1, o);
        }
        if (lane < 4) {
            atomicAdd(sumb + col, s0); atomicAdd(sqb + col, q0);
            atomicAdd(sumb + col + 1, s1); atomicAdd(sqb + col + 1, q1);
        }
    }
}

// ---------------- BN finalize ----------------
__global__ void bn_finalize(const float* __restrict__ gamma,
                            const float* __restrict__ beta, int which) {
    int c = threadIdx.x;
    const float inv_n = 1.f / (float)NPIX;
    float mean = g_stats[which*512 + c] * inv_n;
    float var  = g_stats[which*512 + 256 + c] * inv_n - mean*mean;
    float sc = gamma[c] * rsqrtf(var + 1e-5f);
    g_bn[which*512 + c] = sc;
    g_bn[which*512 + 256 + c] = fmaf(-mean, sc, beta[c]);
}

// ---------------- BN-A apply + relu + fp16 convert ----------------
__global__ void bn_convert(const float* __restrict__ in, __half* __restrict__ a3) {
    __shared__ float sc[256], sh[256];
    if (threadIdx.x < 256) {
        sc[threadIdx.x] = g_bn[threadIdx.x];
        sh[threadIdx.x] = g_bn[256 + threadIdx.x];
    }
    __syncthreads();
    const float4* in4 = (const float4*)in;
    const int total4 = NPIX * 64;
    for (int i = blockIdx.x*blockDim.x + threadIdx.x; i < total4; i += gridDim.x*blockDim.x) {
        float4 v = in4[i];
        int c = (i & 63) * 4;
        size_t pix = (size_t)(i >> 6);
        float f[4] = {v.x, v.y, v.z, v.w};
        __half h[4];
        #pragma unroll
        for (int cc = 0; cc < 4; cc++)
            h[cc] = __float2half_rn(fmaxf(fmaf(f[cc], sc[c+cc], sh[c+cc]), 0.f));
        uint2 pk = make_uint2(
            ((uint32_t)__half_as_ushort(h[0])) | ((uint32_t)__half_as_ushort(h[1]) << 16),
            ((uint32_t)__half_as_ushort(h[2])) | ((uint32_t)__half_as_ushort(h[3]) << 16));
        *(uint2*)(a3 + pix*KROW + c) = pk;
    }
}

// ---------------- BN-B apply + relu + HWC->NCHW ----------------
__global__ void __launch_bounds__(256) bn_apply_nchw(const float* __restrict__ in,
                                                     float* __restrict__ out) {
    __shared__ float s[32*257];
    const int tid = threadIdx.x;
    const float sc = g_bn[512 + tid];
    const float sh = g_bn[768 + tid];
    const int xy0 = blockIdx.x * 32;
    #pragma unroll
    for (int m = 0; m < 32; m++) {
        float v = in[(size_t)(xy0 + m)*CO + tid];
        s[m*257 + tid] = fmaxf(fmaf(v, sc, sh), 0.f);
    }
    __syncthreads();
    #pragma unroll
    for (int m = 0; m < 32; m++) {
        int o = m*8 + (tid >> 5);
        int xyl = tid & 31;
        out[(size_t)o*NPIX + xy0 + xyl] = s[xyl*257 + o];
    }
}

// ---------------- launch ----------------
extern "C" void kernel_launch(void* const* d_in, const int* in_sizes, int n_in,
                              void* d_out, int out_size) {
    const float* pillars = (const float*)d_in[0];
    const int*   nump    = (const int*)d_in[1];
    const int*   indices = (const int*)d_in[2];
    const float* w1   = (const float*)d_in[3];
    const float* b1   = (const float*)d_in[4];
    const float* w2   = (const float*)d_in[5];
    const float* b2   = (const float*)d_in[6];
    const float* c1w  = (const float*)d_in[7];
    const float* c1b  = (const float*)d_in[8];
    const float* cAw  = (const float*)d_in[9];
    const float* cAb  = (const float*)d_in[10];
    const float* bnAg = (const float*)d_in[11];
    const float* bnAb = (const float*)d_in[12];
    const float* cBw  = (const float*)d_in[13];
    const float* cBb  = (const float*)d_in[14];
    const float* bnBg = (const float*)d_in[15];
    const float* bnBb = (const float*)d_in[16];
    float* out = (float*)d_out;

    float *p_buf1, *p_buf2, *p_stats;
    __half *p_a3a, *p_a3b, *p_bA, *p_bB;
    cudaGetSymbolAddress((void**)&p_buf1,  g_buf1);
    cudaGetSymbolAddress((void**)&p_buf2,  g_buf2);
    cudaGetSymbolAddress((void**)&p_stats, g_stats);
    cudaGetSymbolAddress((void**)&p_a3a,   g_a3a);
    cudaGetSymbolAddress((void**)&p_a3b,   g_a3b);
    cudaGetSymbolAddress((void**)&p_bA,    g_bA);
    cudaGetSymbolAddress((void**)&p_bB,    g_bB);

    static bool attr_done = false;
    if (!attr_done) {
        cudaFuncSetAttribute(conv_mma, cudaFuncAttributeMaxDynamicSharedMemorySize, 99328);
        attr_done = true;
    }

    zero_stats<<<1, 256>>>();
    prep_weights<<<1200, 256>>>(c1w, w2, cAw, cBw);
    init_a3<<<2048, 256>>>(c1b, p_a3a);
    pillar_fused<<<VNUM/8, 256, 49152>>>(pillars, nump, indices, w1, b1, b2, c1b, p_a3a);

    dim3 cgrid(2048, 2);
    conv_mma<<<cgrid, 256, 99328>>>(p_a3a, p_bA, cAb, p_buf1, p_stats, p_stats + 256);
    bn_finalize<<<1, 256>>>(bnAg, bnAb, 0);

    bn_convert<<<4096, 256>>>(p_buf1, p_a3b);

    conv_mma<<<cgrid, 256, 99328>>>(p_a3b, p_bB, cBb, p_buf2, p_stats + 512, p_stats + 768);
    bn_finalize<<<1, 256>>>(bnBg, bnBb, 1);

    bn_apply_nchw<<<NPIX/32, 256>>>(p_buf2, out);
}

// round 10
// speedup vs baseline: 1.6144x; 1.0240x over previous
#include <cuda_runtime.h>
#include <cuda_bf16.h>
#include <cuda_fp16.h>
#include <cstdint>

#define XDIM 512
#define YDIM 512
#define NPIX (XDIM*YDIM)      // 262144
#define VNUM 150000
#define HID 64
#define CO 256
#define KEFF 2304             // 9 taps * 256 ch (single fp16 slot)
#define KROW 256              // per-pixel slots

// ---------------- scratch ----------------
__device__ __align__(256) __half g_h16[(size_t)NPIX*CO];   // pre-BN conv out (reused A/B)
__device__ __align__(256) __half g_a3a[(size_t)NPIX*KROW];
__device__ __align__(256) __half g_a3b[(size_t)NPIX*KROW];
__device__ __align__(256) float g_wt1[HID*CO];          // conv1 W^T [c][o]
__device__ __align__(256) __half g_w2h[HID*HID];        // w2 fp16 [g][h]
__device__ __align__(256) __half g_bA[(size_t)CO*KEFF];
__device__ __align__(256) __half g_bB[(size_t)CO*KEFF];
__device__ __align__(256) float g_stats[4*CO];
__device__ __align__(256) float g_bn[4*CO];

__device__ __forceinline__ uint32_t smem_u32(const void* p) {
    uint32_t a;
    asm("{ .reg .u64 t; cvta.to.shared.u64 t, %1; cvt.u32.u64 %0, t; }" : "=r"(a) : "l"(p));
    return a;
}

#define LDSM_X4(r0,r1,r2,r3,addr) \
    asm volatile("ldmatrix.sync.aligned.m8n8.x4.shared.b16 {%0,%1,%2,%3}, [%4];" \
        : "=r"(r0),"=r"(r1),"=r"(r2),"=r"(r3) : "r"(addr))
#define MMA_F16(d, a, b) \
    asm volatile("mma.sync.aligned.m16n8k16.row.col.f32.f16.f16.f32 " \
        "{%0,%1,%2,%3},{%4,%5,%6,%7},{%8,%9},{%0,%1,%2,%3};" \
        : "+f"((d)[0]),"+f"((d)[1]),"+f"((d)[2]),"+f"((d)[3]) \
        : "r"((a)[0]),"r"((a)[1]),"r"((a)[2]),"r"((a)[3]),"r"((b)[0]),"r"((b)[1]))
#define CP_ASYNC(dst, src, sz) \
    asm volatile("cp.async.cg.shared.global [%0], [%1], 16, %2;" \
        :: "r"(dst), "l"(src), "r"(sz))
#define CP_COMMIT() asm volatile("cp.async.commit_group;")
#define CP_WAIT1()  asm volatile("cp.async.wait_group 1;")
#define CP_WAIT0()  asm volatile("cp.async.wait_group 0;")

// ---------------- zero stats ----------------
__global__ void zero_stats() {
    for (int i = threadIdx.x; i < 4*CO; i += blockDim.x) g_stats[i] = 0.f;
}

// ---------------- init a3a = fp16(conv1 bias) everywhere ----------------
__global__ void init_a3(const float* __restrict__ bias, __half* __restrict__ a3) {
    __shared__ __half hb[256];
    if (threadIdx.x < 256) hb[threadIdx.x] = __float2half_rn(bias[threadIdx.x]);
    __syncthreads();
    uint4* dst = (uint4*)a3;
    const uint4* src = (const uint4*)hb;
    const int total = NPIX*256/8;
    for (int i = blockIdx.x*blockDim.x + threadIdx.x; i < total; i += gridDim.x*blockDim.x)
        dst[i] = src[i & 31];
}

// ---------------- weight prep ----------------
__global__ void prep_weights(const float* __restrict__ c1w,
                             const float* __restrict__ w2,
                             const float* __restrict__ cAw,
                             const float* __restrict__ cBw) {
    const int total1 = HID*CO;        // 16384
    const int totalw2 = HID*HID;      // 4096
    const int totalc = CO*CO*9;       // 589824
    const int grand = total1 + totalw2 + 2*totalc;
    for (int i = blockIdx.x*blockDim.x + threadIdx.x; i < grand;
         i += gridDim.x*blockDim.x) {
        if (i < total1) {
            int o = i & 255, c = i >> 8;
            g_wt1[i] = c1w[o*HID + c];
        } else if (i < total1 + totalw2) {
            int j = i - total1;
            g_w2h[j] = __float2half_rn(w2[j]);
        } else {
            int j = i - total1 - totalw2;
            const float* src = cAw; __half* dst = g_bA;
            if (j >= totalc) { j -= totalc; src = cBw; dst = g_bB; }
            int o = j / 2304, k = j % 2304;
            int c = k / 9, tap = k % 9;
            float w = src[(size_t)o*2304 + c*9 + tap];
            dst[(size_t)o*KEFF + tap*KROW + c] = __float2half_rn(w);
        }
    }
}

// ---------------- fused pillar MLP (HMMA stage2) + pool + conv1 + scatter ----
__global__ void __launch_bounds__(256, 2) pillar_fused(
    const float* __restrict__ pillars, const int* __restrict__ nump,
    const int* __restrict__ indices, const float* __restrict__ w1,
    const float* __restrict__ b1, const float* __restrict__ b2,
    const float* __restrict__ c1b, __half* __restrict__ a3)
{
    extern __shared__ char sm[];
    const int tid = threadIdx.x, lane = tid & 31, wid = tid >> 5;
    const uint32_t sb = smem_u32(sm);
    const int v0 = blockIdx.x * 8;

    float4* pts4   = (float4*)(sm + 40960);
    float*  pooled = (float*)(sm + 45056);
    float*  w1s    = (float*)(sm + 47104);
    float*  b1s    = (float*)(sm + 48128);
    float*  b2s    = (float*)(sm + 48384);
    float*  maskf  = (float*)(sm + 48640);
    int*    sxy    = (int*)(sm + 48672);

    w1s[tid] = w1[tid];
    if (tid < 64) { b1s[tid] = b1[tid]; b2s[tid] = b2[tid]; }
    if (tid < 8) {
        int v = v0 + tid;
        maskf[tid] = (nump[v] > 0) ? 1.f : 0.f;
        int xv = indices[2*v], yv = indices[2*v + 1];
        sxy[tid] = ((unsigned)xv < XDIM && (unsigned)yv < YDIM) ? xv*YDIM + yv : -1;
    }
    pts4[tid] = *(const float4*)(pillars + (size_t)v0*128 + tid*4);
    {
        const uint4* w2g = (const uint4*)g_w2h;
        #pragma unroll
        for (int i = 0; i < 2; i++) {
            int idx = tid*2 + i;
            int g = idx >> 3, grp = idx & 7;
            uint32_t off = 32768u + (uint32_t)((g*128 + grp*16) ^ ((g & 7) << 4));
            *(uint4*)(sm + off) = w2g[idx];
        }
    }
    __syncthreads();

    // ---- stage A ----
    {
        float4 x = pts4[tid];
        float m = maskf[tid >> 5];
        x.x *= m; x.y *= m; x.z *= m; x.w *= m;
        const int phase = (tid >> 3) & 7;
        #pragma unroll
        for (int g8 = 0; g8 < 8; g8++) {
            int grp = (g8 + phase) & 7;
            uint32_t pk[4];
            #pragma unroll
            for (int u = 0; u < 4; u++) {
                int t0 = grp*8 + u*2;
                float4 wa = *(float4*)&w1s[t0*4];
                float4 wb = *(float4*)&w1s[t0*4 + 4];
                float h0 = fmaf(wa.x, x.x, fmaf(wa.y, x.y, fmaf(wa.z, x.z, fmaf(wa.w, x.w, b1s[t0]))));
                float h1v = fmaf(wb.x, x.x, fmaf(wb.y, x.y, fmaf(wb.z, x.z, fmaf(wb.w, x.w, b1s[t0+1]))));
                __half2 hh = __floats2half2_rn(fmaxf(h0, 0.f), fmaxf(h1v, 0.f));
                pk[u] = *(uint32_t*)&hh;
            }
            uint32_t off = (uint32_t)((tid*128 + grp*16) ^ ((tid & 7) << 4));
            *(uint4*)(sm + off) = make_uint4(pk[0], pk[1], pk[2], pk[3]);
        }
    }
    __syncthreads();

    // ---- stage B ----
    const int a_row = wid*32 + (lane & 15);
    const int a_kb  = (lane >> 4) * 16;
    const int b_row = ((lane & 16) >> 1) + (lane & 7);
    const int b_kb  = (lane & 8) ? 16 : 0;

    float acc[2][8][4];
    #pragma unroll
    for (int i = 0; i < 2; i++)
        #pragma unroll
        for (int j = 0; j < 8; j++)
            #pragma unroll
            for (int k = 0; k < 4; k++) acc[i][j][k] = 0.f;

    #pragma unroll
    for (int ks = 0; ks < 4; ks++) {
        uint32_t af[2][4], bf[8][2];
        #pragma unroll
        for (int mt = 0; mt < 2; mt++) {
            uint32_t off = (a_row + mt*16)*128 + a_kb + ks*32;
            off ^= (off >> 3) & 0x70;
            LDSM_X4(af[mt][0], af[mt][1], af[mt][2], af[mt][3], sb + off);
        }
        #pragma unroll
        for (int pr = 0; pr < 4; pr++) {
            uint32_t off = (b_row + pr*16)*128 + b_kb + ks*32;
            off ^= (off >> 3) & 0x70;
            LDSM_X4(bf[pr*2][0], bf[pr*2][1], bf[pr*2+1][0], bf[pr*2+1][1], sb + 32768u + off);
        }
        #pragma unroll
        for (int mt = 0; mt < 2; mt++)
            #pragma unroll
            for (int nt = 0; nt < 8; nt++)
                MMA_F16(acc[mt][nt], af[mt], bf[nt]);
    }

    #pragma unroll
    for (int nt = 0; nt < 8; nt++) {
        const int col = nt*8 + (lane & 3)*2;
        const float bb0 = b2s[col], bb1 = b2s[col + 1];
        float s0 = fmaxf(acc[0][nt][0] + bb0, 0.f) + fmaxf(acc[0][nt][2] + bb0, 0.f)
                 + fmaxf(acc[1][nt][0] + bb0, 0.f) + fmaxf(acc[1][nt][2] + bb0, 0.f);
        float s1 = fmaxf(acc[0][nt][1] + bb1, 0.f) + fmaxf(acc[0][nt][3] + bb1, 0.f)
                 + fmaxf(acc[1][nt][1] + bb1, 0.f) + fmaxf(acc[1][nt][3] + bb1, 0.f);
        #pragma unroll
        for (int o = 4; o < 32; o <<= 1) {
            s0 += __shfl_xor_sync(0xffffffffu, s0, o);
            s1 += __shfl_xor_sync(0xffffffffu, s1, o);
        }
        if (lane < 4) {
            pooled[wid*64 + col]     = s0 * (1.f/32.f);
            pooled[wid*64 + col + 1] = s1 * (1.f/32.f);
        }
    }
    __syncthreads();

    // ---- stage C ----
    float wv[64];
    #pragma unroll
    for (int c = 0; c < 64; c++) wv[c] = g_wt1[c*CO + tid];
    float accp[8];
    const float bo = c1b[tid];
    #pragma unroll
    for (int p = 0; p < 8; p++) accp[p] = bo;
    const float4* pool4 = (const float4*)pooled;
    #pragma unroll
    for (int c4 = 0; c4 < 16; c4++) {
        #pragma unroll
        for (int p = 0; p < 8; p++) {
            float4 pv = pool4[p*16 + c4];
            accp[p] = fmaf(wv[c4*4],   pv.x, accp[p]);
            accp[p] = fmaf(wv[c4*4+1], pv.y, accp[p]);
            accp[p] = fmaf(wv[c4*4+2], pv.z, accp[p]);
            accp[p] = fmaf(wv[c4*4+3], pv.w, accp[p]);
        }
    }
    #pragma unroll
    for (int p = 0; p < 8; p++) {
        int xy = sxy[p];
        if (xy >= 0) a3[(size_t)xy*KROW + tid] = __float2half_rn(accp[p]);
    }
}

// ---------------- mma.sync 3x3 conv: fp16 output (pre-BN), fp32 stats -------
__global__ void __launch_bounds__(256, 2) conv_mma(
    const __half* __restrict__ a3w, const __half* __restrict__ b3w,
    const float* __restrict__ bias, __half* __restrict__ out,
    float* __restrict__ sumb, float* __restrict__ sqb)
{
    extern __shared__ char sm[];
    const char* a3 = (const char*)a3w;
    const char* b3 = (const char*)b3w;
    const int tid = threadIdx.x, wid = tid >> 5, lane = tid & 31;
    const int wm = wid >> 2, wn = wid & 3;
    const uint32_t sb = smem_u32(sm);
    float* sbias = (float*)(sm + 98304);

    const int xr = blockIdx.x >> 2;
    const int y0 = (blockIdx.x & 3) * 128;
    const int p0 = xr*512 + y0;
    const int o0 = blockIdx.y * 128;

    sbias[tid] = bias[tid];

    const int a_row = wm*64 + (lane & 15);
    const int a_kb  = (lane >> 4) * 16;
    const int b_row = wn*32 + ((lane & 16) >> 1) + (lane & 7);
    const int b_kb  = (lane & 8) ? 16 : 0;

    const int l_row = tid >> 3;
    const int l_j   = (tid & 7) * 16;

    float acc[4][4][4];
    #pragma unroll
    for (int i = 0; i < 4; i++)
        #pragma unroll
        for (int j = 0; j < 4; j++)
            #pragma unroll
            for (int k = 0; k < 4; k++) acc[i][j][k] = 0.f;

    auto load_chunk = [&](int c, int slot) {
        const int tap = c >> 2, kc = c & 3;
        const int dx = tap/3 - 1, dyy = tap - (tap/3)*3 - 1;
        const int xx = xr + dx;
        const bool xok = (unsigned)xx < XDIM;
        const uint32_t abase = sb + slot*32768u;
        const uint32_t bbase = abase + 16384u;
        #pragma unroll
        for (int i = 0; i < 4; i++) {
            int row = l_row + i*32;
            int yy = y0 + row + dyy;
            bool ok = xok && ((unsigned)yy < YDIM);
            const char* src = ok ? (a3 + ((size_t)(xx*512 + yy))*512 + kc*128 + l_j)
                                 : a3;
            uint32_t off = row*128 + l_j; off ^= (off >> 3) & 0x70;
            CP_ASYNC(abase + off, src, ok ? 16 : 0);
        }
        #pragma unroll
        for (int i = 0; i < 4; i++) {
            int row = l_row + i*32;
            const char* src = b3 + (size_t)(o0 + row)*4608 + tap*512 + kc*128 + l_j;
            uint32_t off = row*128 + l_j; off ^= (off >> 3) & 0x70;
            CP_ASYNC(bbase + off, src, 16);
        }
    };

    load_chunk(0, 0); CP_COMMIT();
    load_chunk(1, 1); CP_COMMIT();

    for (int c = 0; c < 36; c++) {
        if (c < 35) CP_WAIT1(); else CP_WAIT0();
        __syncthreads();
        if (c + 2 < 36) { load_chunk(c + 2, (c + 2) % 3); CP_COMMIT(); }

        const uint32_t sa  = sb + (uint32_t)(c % 3)*32768u;
        const uint32_t sbm = sa + 16384u;
        #pragma unroll
        for (int ks = 0; ks < 4; ks++) {
            uint32_t af[4][4], bf[4][2];
            #pragma unroll
            for (int mt = 0; mt < 4; mt++) {
                uint32_t off = (a_row + mt*16)*128 + a_kb + ks*32;
                off ^= (off >> 3) & 0x70;
                LDSM_X4(af[mt][0], af[mt][1], af[mt][2], af[mt][3], sa + off);
            }
            #pragma unroll
            for (int pr = 0; pr < 2; pr++) {
                uint32_t off = (b_row + pr*16)*128 + b_kb + ks*32;
                off ^= (off >> 3) & 0x70;
                LDSM_X4(bf[pr*2][0], bf[pr*2][1], bf[pr*2+1][0], bf[pr*2+1][1], sbm + off);
            }
            #pragma unroll
            for (int mt = 0; mt < 4; mt++)
                #pragma unroll
                for (int nt = 0; nt < 4; nt++)
                    MMA_F16(acc[mt][nt], af[mt], bf[nt]);
        }
    }

    // epilogue: bias add, fp16 HWC store, fp32 BN stats
    #pragma unroll
    for (int nt = 0; nt < 4; nt++) {
        const int col = o0 + wn*32 + nt*8 + (lane & 3)*2;
        const float bs0 = sbias[col];
        const float bs1 = sbias[col + 1];
        float s0 = 0.f, q0 = 0.f, s1 = 0.f, q1 = 0.f;
        #pragma unroll
        for (int mt = 0; mt < 4; mt++) {
            const int prow = p0 + wm*64 + mt*16 + (lane >> 2);
            float v00 = acc[mt][nt][0] + bs0;
            float v01 = acc[mt][nt][1] + bs1;
            float v10 = acc[mt][nt][2] + bs0;
            float v11 = acc[mt][nt][3] + bs1;
            __half2 h0 = __floats2half2_rn(v00, v01);
            __half2 h1 = __floats2half2_rn(v10, v11);
            *(__half2*)(out + (size_t)prow*CO + col)     = h0;
            *(__half2*)(out + (size_t)(prow+8)*CO + col) = h1;
            s0 += v00 + v10; q0 += v00*v00 + v10*v10;
            s1 += v01 + v11; q1 += v01*v01 + v11*v11;
        }
        #pragma unroll
        for (int o = 4; o < 32; o <<= 1) {
            s0 += __shfl_xor_sync(0xffffffffu, s0, o);
            q0 += __shfl_xor_sync(0xffffffffu, q0, o);
            s1 += __shfl_xor_sync(0xffffffffu, s1, o);
            q1 += __shfl_xor_sync(0xffffffffu, q1, o);
        }
        if (lane < 4) {
            atomicAdd(sumb + col, s0); atomicAdd(sqb + col, q0);
            atomicAdd(sumb + col + 1, s1); atomicAdd(sqb + col + 1, q1);
        }
    }
}

// ---------------- BN finalize ----------------
__global__ void bn_finalize(const float* __restrict__ gamma,
                            const float* __restrict__ beta, int which) {
    int c = threadIdx.x;
    const float inv_n = 1.f / (float)NPIX;
    float mean = g_stats[which*512 + c] * inv_n;
    float var  = g_stats[which*512 + 256 + c] * inv_n - mean*mean;
    float sc = gamma[c] * rsqrtf(var + 1e-5f);
    g_bn[which*512 + c] = sc;
    g_bn[which*512 + 256 + c] = fmaf(-mean, sc, beta[c]);
}

// ---------------- BN-A apply + relu + fp16 convert (fp16 in) ----------------
__global__ void bn_convert(const __half* __restrict__ in, __half* __restrict__ a3) {
    __shared__ float sc[256], sh[256];
    if (threadIdx.x < 256) {
        sc[threadIdx.x] = g_bn[threadIdx.x];
        sh[threadIdx.x] = g_bn[256 + threadIdx.x];
    }
    __syncthreads();
    const uint2* in4 = (const uint2*)in;      // 4 halfs per uint2
    const int total4 = NPIX * 64;
    for (int i = blockIdx.x*blockDim.x + threadIdx.x; i < total4; i += gridDim.x*blockDim.x) {
        uint2 raw = in4[i];
        __half2 p0 = *(__half2*)&raw.x;
        __half2 p1 = *(__half2*)&raw.y;
        int c = (i & 63) * 4;
        float f[4] = { __low2float(p0), __high2float(p0), __low2float(p1), __high2float(p1) };
        __half h[4];
        #pragma unroll
        for (int cc = 0; cc < 4; cc++)
            h[cc] = __float2half_rn(fmaxf(fmaf(f[cc], sc[c+cc], sh[c+cc]), 0.f));
        uint2 pk = make_uint2(
            ((uint32_t)__half_as_ushort(h[0])) | ((uint32_t)__half_as_ushort(h[1]) << 16),
            ((uint32_t)__half_as_ushort(h[2])) | ((uint32_t)__half_as_ushort(h[3]) << 16));
        ((uint2*)a3)[i] = pk;
    }
}

// ---------------- BN-B apply + relu + HWC->NCHW (fp16 in, fp32 out) ---------
__global__ void __launch_bounds__(256) bn_apply_nchw(const __half* __restrict__ in,
                                                     float* __restrict__ out) {
    __shared__ float s[32*257];
    const int tid = threadIdx.x;
    const float sc = g_bn[512 + tid];
    const float sh = g_bn[768 + tid];
    const int xy0 = blockIdx.x * 32;
    #pragma unroll
    for (int m = 0; m < 32; m++) {
        float v = __half2float(in[(size_t)(xy0 + m)*CO + tid]);
        s[m*257 + tid] = fmaxf(fmaf(v, sc, sh), 0.f);
    }
    __syncthreads();
    #pragma unroll
    for (int m = 0; m < 32; m++) {
        int o = m*8 + (tid >> 5);
        int xyl = tid & 31;
        out[(size_t)o*NPIX + xy0 + xyl] = s[xyl*257 + o];
    }
}

// ---------------- launch ----------------
extern "C" void kernel_launch(void* const* d_in, const int* in_sizes, int n_in,
                              void* d_out, int out_size) {
    const float* pillars = (const float*)d_in[0];
    const int*   nump    = (const int*)d_in[1];
    const int*   indices = (const int*)d_in[2];
    const float* w1   = (const float*)d_in[3];
    const float* b1   = (const float*)d_in[4];
    const float* w2   = (const float*)d_in[5];
    const float* b2   = (const float*)d_in[6];
    const float* c1w  = (const float*)d_in[7];
    const float* c1b  = (const float*)d_in[8];
    const float* cAw  = (const float*)d_in[9];
    const float* cAb  = (const float*)d_in[10];
    const float* bnAg = (const float*)d_in[11];
    const float* bnAb = (const float*)d_in[12];
    const float* cBw  = (const float*)d_in[13];
    const float* cBb  = (const float*)d_in[14];
    const float* bnBg = (const float*)d_in[15];
    const float* bnBb = (const float*)d_in[16];
    float* out = (float*)d_out;

    float *p_stats;
    __half *p_h16, *p_a3a, *p_a3b, *p_bA, *p_bB;
    cudaGetSymbolAddress((void**)&p_h16,   g_h16);
    cudaGetSymbolAddress((void**)&p_stats, g_stats);
    cudaGetSymbolAddress((void**)&p_a3a,   g_a3a);
    cudaGetSymbolAddress((void**)&p_a3b,   g_a3b);
    cudaGetSymbolAddress((void**)&p_bA,    g_bA);
    cudaGetSymbolAddress((void**)&p_bB,    g_bB);

    static bool attr_done = false;
    if (!attr_done) {
        cudaFuncSetAttribute(conv_mma, cudaFuncAttributeMaxDynamicSharedMemorySize, 99328);
        attr_done = true;
    }

    zero_stats<<<1, 256>>>();
    prep_weights<<<1200, 256>>>(c1w, w2, cAw, cBw);
    init_a3<<<2048, 256>>>(c1b, p_a3a);
    pillar_fused<<<VNUM/8, 256, 49152>>>(pillars, nump, indices, w1, b1, b2, c1b, p_a3a);

    dim3 cgrid(2048, 2);
    conv_mma<<<cgrid, 256, 99328>>>(p_a3a, p_bA, cAb, p_h16, p_stats, p_stats + 256);
    bn_finalize<<<1, 256>>>(bnAg, bnAb, 0);

    bn_convert<<<4096, 256>>>(p_h16, p_a3b);

    conv_mma<<<cgrid, 256, 99328>>>(p_a3b, p_bB, cBb, p_h16, p_stats + 512, p_stats + 768);
    bn_finalize<<<1, 256>>>(bnBg, bnBb, 1);

    bn_apply_nchw<<<NPIX/32, 256>>>(p_h16, out);
}

// round 12
// speedup vs baseline: 2.3235x; 1.4393x over previous
#include <cuda_runtime.h>
#include <cuda_bf16.h>
#include <cuda_fp16.h>
#include <cstdint>

#define XDIM 512
#define YDIM 512
#define NPIX (XDIM*YDIM)      // 262144
#define VNUM 150000
#define HID 64
#define CO 256
#define KEFF 2304             // convB: 9 taps * 256 ch
#define KROW 256              // convB input row (halves)

// ---------------- scratch ----------------
__device__ __align__(256) __half g_h16[(size_t)NPIX*CO];   // pre-BN conv out (reused A/B)
__device__ __align__(256) __half g_a3a[(size_t)NPIX*HID];  // pooled BEV, 64ch fp16 (32MB)
__device__ __align__(256) __half g_a3b[(size_t)NPIX*KROW]; // convB input 256ch fp16
__device__ __align__(256) __half g_w2h[HID*HID];           // w2 fp16 [g][h]
__device__ __align__(256) __half g_weff[(size_t)CO*576];   // folded convA: [o][tap*64+h]
__device__ __align__(256) float g_bvec[9*CO];              // per-tap folded bias [tap][o]
__device__ __align__(256) __half g_bB[(size_t)CO*KEFF];    // convB weights [o][tap*256+c]
__device__ __align__(256) float g_stats[4*CO];
__device__ __align__(256) float g_bn[4*CO];

__device__ __forceinline__ uint32_t smem_u32(const void* p) {
    uint32_t a;
    asm("{ .reg .u64 t; cvta.to.shared.u64 t, %1; cvt.u32.u64 %0, t; }" : "=r"(a) : "l"(p));
    return a;
}

#define LDSM_X4(r0,r1,r2,r3,addr) \
    asm volatile("ldmatrix.sync.aligned.m8n8.x4.shared.b16 {%0,%1,%2,%3}, [%4];" \
        : "=r"(r0),"=r"(r1),"=r"(r2),"=r"(r3) : "r"(addr))
#define MMA_F16(d, a, b) \
    asm volatile("mma.sync.aligned.m16n8k16.row.col.f32.f16.f16.f32 " \
        "{%0,%1,%2,%3},{%4,%5,%6,%7},{%8,%9},{%0,%1,%2,%3};" \
        : "+f"((d)[0]),"+f"((d)[1]),"+f"((d)[2]),"+f"((d)[3]) \
        : "r"((a)[0]),"r"((a)[1]),"r"((a)[2]),"r"((a)[3]),"r"((b)[0]),"r"((b)[1]))
#define CP_ASYNC(dst, src, sz) \
    asm volatile("cp.async.cg.shared.global [%0], [%1], 16, %2;" \
        :: "r"(dst), "l"(src), "r"(sz))
#define CP_COMMIT() asm volatile("cp.async.commit_group;")
#define CP_WAIT1()  asm volatile("cp.async.wait_group 1;")
#define CP_WAIT0()  asm volatile("cp.async.wait_group 0;")

// ---------------- zero stats + zero a3a ----------------
__global__ void zero_kernel() {
    uint4* p = (uint4*)g_a3a;
    const int n16 = NPIX*HID*2/16;      // 2M uint4
    uint4 z = make_uint4(0,0,0,0);
    for (int i = blockIdx.x*blockDim.x + threadIdx.x; i < n16; i += gridDim.x*blockDim.x)
        p[i] = z;
    if (blockIdx.x == 0)
        for (int i = threadIdx.x; i < 4*CO; i += blockDim.x) g_stats[i] = 0.f;
}

// ---------------- weight prep: w2 fp16 + convB fp16 ----------------
__global__ void prep_weights(const float* __restrict__ w2,
                             const float* __restrict__ cBw) {
    const int totalw2 = HID*HID;      // 4096
    const int totalc = CO*CO*9;       // 589824
    for (int i = blockIdx.x*blockDim.x + threadIdx.x; i < totalw2 + totalc;
         i += gridDim.x*blockDim.x) {
        if (i < totalw2) {
            g_w2h[i] = __float2half_rn(w2[i]);
        } else {
            int j = i - totalw2;
            int o = j / 2304, k = j % 2304;
            int c = k / 9, tap = k % 9;
            g_bB[(size_t)o*KEFF + tap*KROW + c] = __float2half_rn(cBw[(size_t)o*2304 + c*9 + tap]);
        }
    }
}

// ---------------- fold conv1 into convA: weff + bvec (cAb folded into tap 4) -
__global__ void __launch_bounds__(64) prep_weff(
    const float* __restrict__ cAw, const float* __restrict__ c1w,
    const float* __restrict__ c1b, const float* __restrict__ cAb) {
    const int o = blockIdx.x / 9, tap = blockIdx.x % 9;
    const int h = threadIdx.x;
    const float* arow = cAw + (size_t)o*2304 + tap;   // stride 9 over c
    float s = 0.f;
    for (int c = 0; c < 256; c++)
        s = fmaf(arow[c*9], c1w[c*64 + h], s);
    g_weff[(size_t)o*576 + tap*64 + h] = __float2half_rn(s);
    if (h == 0) {
        float sb = 0.f;
        for (int c = 0; c < 256; c++) sb = fmaf(arow[c*9], c1b[c], sb);
        if (tap == 4) sb += cAb[o];   // center tap always in-bounds
        g_bvec[tap*256 + o] = sb;
    }
}

// ---------------- fused pillar MLP (HMMA stage2) + pool + scatter ----------
__global__ void __launch_bounds__(256, 2) pillar_fused(
    const float* __restrict__ pillars, const int* __restrict__ nump,
    const int* __restrict__ indices, const float* __restrict__ w1,
    const float* __restrict__ b1, const float* __restrict__ b2,
    __half* __restrict__ a3)
{
    extern __shared__ char sm[];
    const int tid = threadIdx.x, lane = tid & 31, wid = tid >> 5;
    const uint32_t sb = smem_u32(sm);
    const int v0 = blockIdx.x * 8;

    float4* pts4   = (float4*)(sm + 40960);
    float*  pooled = (float*)(sm + 45056);
    float*  w1s    = (float*)(sm + 47104);
    float*  b1s    = (float*)(sm + 48128);
    float*  b2s    = (float*)(sm + 48384);
    float*  maskf  = (float*)(sm + 48640);
    int*    sxy    = (int*)(sm + 48672);

    w1s[tid] = w1[tid];
    if (tid < 64) { b1s[tid] = b1[tid]; b2s[tid] = b2[tid]; }
    if (tid < 8) {
        int v = v0 + tid;
        maskf[tid] = (nump[v] > 0) ? 1.f : 0.f;
        int xv = indices[2*v], yv = indices[2*v + 1];
        sxy[tid] = ((unsigned)xv < XDIM && (unsigned)yv < YDIM) ? xv*YDIM + yv : -1;
    }
    pts4[tid] = *(const float4*)(pillars + (size_t)v0*128 + tid*4);
    {
        const uint4* w2g = (const uint4*)g_w2h;
        #pragma unroll
        for (int i = 0; i < 2; i++) {
            int idx = tid*2 + i;
            int g = idx >> 3, grp = idx & 7;
            uint32_t off = 32768u + (uint32_t)((g*128 + grp*16) ^ ((g & 7) << 4));
            *(uint4*)(sm + off) = w2g[idx];
        }
    }
    __syncthreads();

    // ---- stage A: h1 = relu(x @ w1^T + b1) ----
    {
        float4 x = pts4[tid];
        float m = maskf[tid >> 5];
        x.x *= m; x.y *= m; x.z *= m; x.w *= m;
        const int phase = (tid >> 3) & 7;
        #pragma unroll
        for (int g8 = 0; g8 < 8; g8++) {
            int grp = (g8 + phase) & 7;
            uint32_t pk[4];
            #pragma unroll
            for (int u = 0; u < 4; u++) {
                int t0 = grp*8 + u*2;
                float4 wa = *(float4*)&w1s[t0*4];
                float4 wb = *(float4*)&w1s[t0*4 + 4];
                float h0 = fmaf(wa.x, x.x, fmaf(wa.y, x.y, fmaf(wa.z, x.z, fmaf(wa.w, x.w, b1s[t0]))));
                float h1v = fmaf(wb.x, x.x, fmaf(wb.y, x.y, fmaf(wb.z, x.z, fmaf(wb.w, x.w, b1s[t0+1]))));
                __half2 hh = __floats2half2_rn(fmaxf(h0, 0.f), fmaxf(h1v, 0.f));
                pk[u] = *(uint32_t*)&hh;
            }
            uint32_t off = (uint32_t)((tid*128 + grp*16) ^ ((tid & 7) << 4));
            *(uint4*)(sm + off) = make_uint4(pk[0], pk[1], pk[2], pk[3]);
        }
    }
    __syncthreads();

    // ---- stage B: per-warp pillar GEMM + bias + relu + pool ----
    const int a_row = wid*32 + (lane & 15);
    const int a_kb  = (lane >> 4) * 16;
    const int b_row = ((lane & 16) >> 1) + (lane & 7);
    const int b_kb  = (lane & 8) ? 16 : 0;

    float acc[2][8][4];
    #pragma unroll
    for (int i = 0; i < 2; i++)
        #pragma unroll
        for (int j = 0; j < 8; j++)
            #pragma unroll
            for (int k = 0; k < 4; k++) acc[i][j][k] = 0.f;

    #pragma unroll
    for (int ks = 0; ks < 4; ks++) {
        uint32_t af[2][4], bf[8][2];
        #pragma unroll
        for (int mt = 0; mt < 2; mt++) {
            uint32_t off = (a_row + mt*16)*128 + a_kb + ks*32;
            off ^= (off >> 3) & 0x70;
            LDSM_X4(af[mt][0], af[mt][1], af[mt][2], af[mt][3], sb + off);
        }
        #pragma unroll
        for (int pr = 0; pr < 4; pr++) {
            uint32_t off = (b_row + pr*16)*128 + b_kb + ks*32;
            off ^= (off >> 3) & 0x70;
            LDSM_X4(bf[pr*2][0], bf[pr*2][1], bf[pr*2+1][0], bf[pr*2+1][1], sb + 32768u + off);
        }
        #pragma unroll
        for (int mt = 0; mt < 2; mt++)
            #pragma unroll
            for (int nt = 0; nt < 8; nt++)
                MMA_F16(acc[mt][nt], af[mt], bf[nt]);
    }

    #pragma unroll
    for (int nt = 0; nt < 8; nt++) {
        const int col = nt*8 + (lane & 3)*2;
        const float bb0 = b2s[col], bb1 = b2s[col + 1];
        float s0 = fmaxf(acc[0][nt][0] + bb0, 0.f) + fmaxf(acc[0][nt][2] + bb0, 0.f)
                 + fmaxf(acc[1][nt][0] + bb0, 0.f) + fmaxf(acc[1][nt][2] + bb0, 0.f);
        float s1 = fmaxf(acc[0][nt][1] + bb1, 0.f) + fmaxf(acc[0][nt][3] + bb1, 0.f)
                 + fmaxf(acc[1][nt][1] + bb1, 0.f) + fmaxf(acc[1][nt][3] + bb1, 0.f);
        #pragma unroll
        for (int o = 4; o < 32; o <<= 1) {
            s0 += __shfl_xor_sync(0xffffffffu, s0, o);
            s1 += __shfl_xor_sync(0xffffffffu, s1, o);
        }
        if (lane < 4) {
            pooled[wid*64 + col]     = s0 * (1.f/32.f);
            pooled[wid*64 + col + 1] = s1 * (1.f/32.f);
        }
    }
    __syncthreads();

    // ---- scatter pooled (fp16, 64ch) into a3a ----
    {
        int p = tid >> 5, c2 = (tid & 31) * 2;
        int xy = sxy[p];
        if (xy >= 0) {
            __half2 hv = __floats2half2_rn(pooled[p*64 + c2], pooled[p*64 + c2 + 1]);
            *(__half2*)(a3 + (size_t)xy*HID + c2) = hv;
        }
    }
}

// ---------------- mma.sync 3x3 conv (FOLD: conv1 folded into convA) --------
template<bool FOLD>
__global__ void __launch_bounds__(256, 2) conv_mma(
    const __half* __restrict__ a3w, const __half* __restrict__ b3w,
    const float* __restrict__ bias, __half* __restrict__ out,
    float* __restrict__ sumb, float* __restrict__ sqb)
{
    extern __shared__ char sm[];
    const char* a3 = (const char*)a3w;
    const char* b3 = (const char*)b3w;
    const int tid = threadIdx.x, wid = tid >> 5, lane = tid & 31;
    const int wm = wid >> 2, wn = wid & 3;
    const uint32_t sb = smem_u32(sm);
    float* sbC = (float*)(sm + 98304);   // indexed by FULL channel 0..255
    float* sbL = (float*)(sm + 99328);
    float* sbH = (float*)(sm + 100352);

    const int xr = blockIdx.x >> 2;
    const int y0 = (blockIdx.x & 3) * 128;
    const int p0 = xr*512 + y0;
    const int o0 = blockIdx.y * 128;

    constexpr int NCHUNK = FOLD ? 9 : 36;
    constexpr int AROWB  = FOLD ? 128 : 512;
    constexpr int BROWB  = FOLD ? 1152 : 4608;

    if (FOLD) {
        float bc = 0.f, bl = 0.f, bh = 0.f;
        #pragma unroll
        for (int tap = 0; tap < 9; tap++) {
            int dx = tap/3 - 1, dy = tap % 3 - 1;
            float bv = bias[tap*256 + tid];
            if ((unsigned)(xr + dx) < XDIM) {
                bc += bv;
                if (dy >= 0) bl += bv;
                if (dy <= 0) bh += bv;
            }
        }
        sbC[tid] = bc; sbL[tid] = bl; sbH[tid] = bh;
    } else {
        sbC[tid] = bias[tid];
    }

    const int a_row = wm*64 + (lane & 15);
    const int a_kb  = (lane >> 4) * 16;
    const int b_row = wn*32 + ((lane & 16) >> 1) + (lane & 7);
    const int b_kb  = (lane & 8) ? 16 : 0;

    const int l_row = tid >> 3;
    const int l_j   = (tid & 7) * 16;

    float acc[4][4][4];
    #pragma unroll
    for (int i = 0; i < 4; i++)
        #pragma unroll
        for (int j = 0; j < 4; j++)
            #pragma unroll
            for (int k = 0; k < 4; k++) acc[i][j][k] = 0.f;

    auto load_chunk = [&](int c, int slot) {
        const int tap = FOLD ? c : (c >> 2);
        const int kc  = FOLD ? 0 : (c & 3);
        const int dx = tap/3 - 1, dyy = tap - (tap/3)*3 - 1;
        const int xx = xr + dx;
        const bool xok = (unsigned)xx < XDIM;
        const uint32_t abase = sb + slot*32768u;
        const uint32_t bbase = abase + 16384u;
        #pragma unroll
        for (int i = 0; i < 4; i++) {
            int row = l_row + i*32;
            int yy = y0 + row + dyy;
            bool ok = xok && ((unsigned)yy < YDIM);
            const char* src = ok ? (a3 + (size_t)(xx*512 + yy)*AROWB + kc*128 + l_j)
                                 : a3;
            uint32_t off = row*128 + l_j; off ^= (off >> 3) & 0x70;
            CP_ASYNC(abase + off, src, ok ? 16 : 0);
        }
        #pragma unroll
        for (int i = 0; i < 4; i++) {
            int row = l_row + i*32;
            const char* src = b3 + (size_t)(o0 + row)*BROWB + c*128 + l_j;
            uint32_t off = row*128 + l_j; off ^= (off >> 3) & 0x70;
            CP_ASYNC(bbase + off, src, 16);
        }
    };

    load_chunk(0, 0); CP_COMMIT();
    load_chunk(1, 1); CP_COMMIT();

    for (int c = 0; c < NCHUNK; c++) {
        if (c < NCHUNK - 1) CP_WAIT1(); else CP_WAIT0();
        __syncthreads();
        if (c + 2 < NCHUNK) { load_chunk(c + 2, (c + 2) % 3); CP_COMMIT(); }

        const uint32_t sa  = sb + (uint32_t)(c % 3)*32768u;
        const uint32_t sbm = sa + 16384u;
        #pragma unroll
        for (int ks = 0; ks < 4; ks++) {
            uint32_t af[4][4], bf[4][2];
            #pragma unroll
            for (int mt = 0; mt < 4; mt++) {
                uint32_t off = (a_row + mt*16)*128 + a_kb + ks*32;
                off ^= (off >> 3) & 0x70;
                LDSM_X4(af[mt][0], af[mt][1], af[mt][2], af[mt][3], sa + off);
            }
            #pragma unroll
            for (int pr = 0; pr < 2; pr++) {
                uint32_t off = (b_row + pr*16)*128 + b_kb + ks*32;
                off ^= (off >> 3) & 0x70;
                LDSM_X4(bf[pr*2][0], bf[pr*2][1], bf[pr*2+1][0], bf[pr*2+1][1], sbm + off);
            }
            #pragma unroll
            for (int mt = 0; mt < 4; mt++)
                #pragma unroll
                for (int nt = 0; nt < 4; nt++)
                    MMA_F16(acc[mt][nt], af[mt], bf[nt]);
        }
    }

    // epilogue: edge-aware bias (FOLD), fp16 HWC store, fp32 BN stats
    #pragma unroll
    for (int nt = 0; nt < 4; nt++) {
        const int col = o0 + wn*32 + nt*8 + (lane & 3)*2;
        const float m0 = sbC[col], m1 = sbC[col + 1];   // FULL channel index
        float s0 = 0.f, q0 = 0.f, s1 = 0.f, q1 = 0.f;
        #pragma unroll
        for (int mt = 0; mt < 4; mt++) {
            const int yoff = wm*64 + mt*16 + (lane >> 2);
            const int prow = p0 + yoff;
            float b0a = m0, b1a = m1, b0b = m0, b1b = m1;
            if (FOLD) {
                int y1 = y0 + yoff;
                if (y1 == 0)       { b0a = sbL[col]; b1a = sbL[col + 1]; }
                if (y1 + 8 == 511) { b0b = sbH[col]; b1b = sbH[col + 1]; }
            }
            float v00 = acc[mt][nt][0] + b0a;
            float v01 = acc[mt][nt][1] + b1a;
            float v10 = acc[mt][nt][2] + b0b;
            float v11 = acc[mt][nt][3] + b1b;
            __half2 h0 = __floats2half2_rn(v00, v01);
            __half2 h1 = __floats2half2_rn(v10, v11);
            *(__half2*)(out + (size_t)prow*CO + col)     = h0;
            *(__half2*)(out + (size_t)(prow+8)*CO + col) = h1;
            s0 += v00 + v10; q0 += v00*v00 + v10*v10;
            s1 += v01 + v11; q1 += v01*v01 + v11*v11;
        }
        #pragma unroll
        for (int o = 4; o < 32; o <<= 1) {
            s0 += __shfl_xor_sync(0xffffffffu, s0, o);
            q0 += __shfl_xor_sync(0xffffffffu, q0, o);
            s1 += __shfl_xor_sync(0xffffffffu, s1, o);
            q1 += __shfl_xor_sync(0xffffffffu, q1, o);
        }
        if (lane < 4) {
            atomicAdd(sumb + col, s0); atomicAdd(sqb + col, q0);
            atomicAdd(sumb + col + 1, s1); atomicAdd(sqb + col + 1, q1);
        }
    }
}

// ---------------- BN finalize ----------------
__global__ void bn_finalize(const float* __restrict__ gamma,
                            const float* __restrict__ beta, int which) {
    int c = threadIdx.x;
    const float inv_n = 1.f / (float)NPIX;
    float mean = g_stats[which*512 + c] * inv_n;
    float var  = g_stats[which*512 + 256 + c] * inv_n - mean*mean;
    float sc = gamma[c] * rsqrtf(var + 1e-5f);
    g_bn[which*512 + c] = sc;
    g_bn[which*512 + 256 + c] = fmaf(-mean, sc, beta[c]);
}

// ---------------- BN-A apply + relu + fp16 convert ----------------
__global__ void bn_convert(const __half* __restrict__ in, __half* __restrict__ a3) {
    __shared__ float sc[256], sh[256];
    if (threadIdx.x < 256) {
        sc[threadIdx.x] = g_bn[threadIdx.x];
        sh[threadIdx.x] = g_bn[256 + threadIdx.x];
    }
    __syncthreads();
    const uint2* in4 = (const uint2*)in;
    const int total4 = NPIX * 64;
    for (int i = blockIdx.x*blockDim.x + threadIdx.x; i < total4; i += gridDim.x*blockDim.x) {
        uint2 raw = in4[i];
        __half2 p0 = *(__half2*)&raw.x;
        __half2 p1 = *(__half2*)&raw.y;
        int c = (i & 63) * 4;
        float f[4] = { __low2float(p0), __high2float(p0), __low2float(p1), __high2float(p1) };
        __half h[4];
        #pragma unroll
        for (int cc = 0; cc < 4; cc++)
            h[cc] = __float2half_rn(fmaxf(fmaf(f[cc], sc[c+cc], sh[c+cc]), 0.f));
        uint2 pk = make_uint2(
            ((uint32_t)__half_as_ushort(h[0])) | ((uint32_t)__half_as_ushort(h[1]) << 16),
            ((uint32_t)__half_as_ushort(h[2])) | ((uint32_t)__half_as_ushort(h[3]) << 16));
        ((uint2*)a3)[i] = pk;
    }
}

// ---------------- BN-B apply + relu + HWC->NCHW ----------------
__global__ void __launch_bounds__(256) bn_apply_nchw(const __half* __restrict__ in,
                                                     float* __restrict__ out) {
    __shared__ float s[32*257];
    const int tid = threadIdx.x;
    const float sc = g_bn[512 + tid];
    const float sh = g_bn[768 + tid];
    const int xy0 = blockIdx.x * 32;
    #pragma unroll
    for (int m = 0; m < 32; m++) {
        float v = __half2float(in[(size_t)(xy0 + m)*CO + tid]);
        s[m*257 + tid] = fmaxf(fmaf(v, sc, sh), 0.f);
    }
    __syncthreads();
    #pragma unroll
    for (int m = 0; m < 32; m++) {
        int o = m*8 + (tid >> 5);
        int xyl = tid & 31;
        out[(size_t)o*NPIX + xy0 + xyl] = s[xyl*257 + o];
    }
}

// ---------------- launch ----------------
extern "C" void kernel_launch(void* const* d_in, const int* in_sizes, int n_in,
                              void* d_out, int out_size) {
    const float* pillars = (const float*)d_in[0];
    const int*   nump    = (const int*)d_in[1];
    const int*   indices = (const int*)d_in[2];
    const float* w1   = (const float*)d_in[3];
    const float* b1   = (const float*)d_in[4];
    const float* w2   = (const float*)d_in[5];
    const float* b2   = (const float*)d_in[6];
    const float* c1w  = (const float*)d_in[7];
    const float* c1b  = (const float*)d_in[8];
    const float* cAw  = (const float*)d_in[9];
    const float* cAb  = (const float*)d_in[10];
    const float* bnAg = (const float*)d_in[11];
    const float* bnAb = (const float*)d_in[12];
    const float* cBw  = (const float*)d_in[13];
    const float* cBb  = (const float*)d_in[14];
    const float* bnBg = (const float*)d_in[15];
    const float* bnBb = (const float*)d_in[16];
    float* out = (float*)d_out;

    float *p_stats, *p_bvec;
    __half *p_h16, *p_a3a, *p_a3b, *p_weff, *p_bB;
    cudaGetSymbolAddress((void**)&p_h16,   g_h16);
    cudaGetSymbolAddress((void**)&p_stats, g_stats);
    cudaGetSymbolAddress((void**)&p_bvec,  g_bvec);
    cudaGetSymbolAddress((void**)&p_a3a,   g_a3a);
    cudaGetSymbolAddress((void**)&p_a3b,   g_a3b);
    cudaGetSymbolAddress((void**)&p_weff,  g_weff);
    cudaGetSymbolAddress((void**)&p_bB,    g_bB);

    static bool attr_done = false;
    if (!attr_done) {
        cudaFuncSetAttribute(conv_mma<true>,  cudaFuncAttributeMaxDynamicSharedMemorySize, 101376);
        cudaFuncSetAttribute(conv_mma<false>, cudaFuncAttributeMaxDynamicSharedMemorySize, 101376);
        attr_done = true;
    }

    zero_kernel<<<2048, 256>>>();
    prep_weights<<<1200, 256>>>(w2, cBw);
    prep_weff<<<CO*9, 64>>>(cAw, c1w, c1b, cAb);
    pillar_fused<<<VNUM/8, 256, 49152>>>(pillars, nump, indices, w1, b1, b2, p_a3a);

    dim3 cgrid(2048, 2);
    // convA (folded, K=576): a3a(64ch) -> h16 + stats
    conv_mma<true><<<cgrid, 256, 101376>>>(p_a3a, p_weff, p_bvec, p_h16, p_stats, p_stats + 256);
    bn_finalize<<<1, 256>>>(bnAg, bnAb, 0);

    bn_convert<<<4096, 256>>>(p_h16, p_a3b);

    // convB (K=2304): a3b -> h16 + stats
    conv_mma<false><<<cgrid, 256, 101376>>>(p_a3b, p_bB, cBb, p_h16, p_stats + 512, p_stats + 768);
    bn_finalize<<<1, 256>>>(bnBg, bnBb, 1);

    bn_apply_nchw<<<NPIX/32, 256>>>(p_h16, out);
}

// round 13
// speedup vs baseline: 2.3247x; 1.0005x over previous
#include <cuda_runtime.h>
#include <cuda_bf16.h>
#include <cuda_fp16.h>
#include <cstdint>

#define XDIM 512
#define YDIM 512
#define NPIX (XDIM*YDIM)      // 262144
#define VNUM 150000
#define HID 64
#define CO 256
#define KEFF 2304             // convB: 9 taps * 256 ch
#define KROW 256              // convB input row (halves)

// ---------------- scratch ----------------
__device__ __align__(256) __half g_h16[(size_t)NPIX*CO];   // pre-BN conv out (reused A/B)
__device__ __align__(256) __half g_a3a[(size_t)NPIX*HID];  // pooled BEV, 64ch fp16 (32MB)
__device__ __align__(256) __half g_a3b[(size_t)NPIX*KROW]; // convB input 256ch fp16
__device__ __align__(256) __half g_w2h[HID*HID];           // w2 fp16 [g][h]
__device__ __align__(256) __half g_weff[(size_t)CO*576];   // folded convA: [o][tap*64+h]
__device__ __align__(256) float g_bvec[9*CO];              // per-tap folded bias [tap][o]
__device__ __align__(256) __half g_bB[(size_t)CO*KEFF];    // convB weights [o][tap*256+c]
__device__ __align__(256) float g_stats[4*CO];
__device__ __align__(256) float g_bn[4*CO];

__device__ __forceinline__ uint32_t smem_u32(const void* p) {
    uint32_t a;
    asm("{ .reg .u64 t; cvta.to.shared.u64 t, %1; cvt.u32.u64 %0, t; }" : "=r"(a) : "l"(p));
    return a;
}

#define LDSM_X4(r0,r1,r2,r3,addr) \
    asm volatile("ldmatrix.sync.aligned.m8n8.x4.shared.b16 {%0,%1,%2,%3}, [%4];" \
        : "=r"(r0),"=r"(r1),"=r"(r2),"=r"(r3) : "r"(addr))
#define MMA_F16(d, a, b) \
    asm volatile("mma.sync.aligned.m16n8k16.row.col.f32.f16.f16.f32 " \
        "{%0,%1,%2,%3},{%4,%5,%6,%7},{%8,%9},{%0,%1,%2,%3};" \
        : "+f"((d)[0]),"+f"((d)[1]),"+f"((d)[2]),"+f"((d)[3]) \
        : "r"((a)[0]),"r"((a)[1]),"r"((a)[2]),"r"((a)[3]),"r"((b)[0]),"r"((b)[1]))
#define CP_ASYNC(dst, src, sz) \
    asm volatile("cp.async.cg.shared.global [%0], [%1], 16, %2;" \
        :: "r"(dst), "l"(src), "r"(sz))
#define CP_COMMIT() asm volatile("cp.async.commit_group;")
#define CP_WAIT1()  asm volatile("cp.async.wait_group 1;")
#define CP_WAIT0()  asm volatile("cp.async.wait_group 0;")

// ---------------- zero stats + zero a3a ----------------
__global__ void zero_kernel() {
    uint4* p = (uint4*)g_a3a;
    const int n16 = NPIX*HID*2/16;      // 2M uint4
    uint4 z = make_uint4(0,0,0,0);
    for (int i = blockIdx.x*blockDim.x + threadIdx.x; i < n16; i += gridDim.x*blockDim.x)
        p[i] = z;
    if (blockIdx.x == 0)
        for (int i = threadIdx.x; i < 4*CO; i += blockDim.x) g_stats[i] = 0.f;
}

// ---------------- weight prep: w2 fp16 + convB fp16 ----------------
__global__ void prep_weights(const float* __restrict__ w2,
                             const float* __restrict__ cBw) {
    const int totalw2 = HID*HID;      // 4096
    const int totalc = CO*CO*9;       // 589824
    for (int i = blockIdx.x*blockDim.x + threadIdx.x; i < totalw2 + totalc;
         i += gridDim.x*blockDim.x) {
        if (i < totalw2) {
            g_w2h[i] = __float2half_rn(w2[i]);
        } else {
            int j = i - totalw2;
            int o = j / 2304, k = j % 2304;
            int c = k / 9, tap = k % 9;
            g_bB[(size_t)o*KEFF + tap*KROW + c] = __float2half_rn(cBw[(size_t)o*2304 + c*9 + tap]);
        }
    }
}

// ---------------- fold conv1 into convA: weff + bvec (cAb folded into tap 4) -
__global__ void __launch_bounds__(64) prep_weff(
    const float* __restrict__ cAw, const float* __restrict__ c1w,
    const float* __restrict__ c1b, const float* __restrict__ cAb) {
    const int o = blockIdx.x / 9, tap = blockIdx.x % 9;
    const int h = threadIdx.x;
    const float* arow = cAw + (size_t)o*2304 + tap;   // stride 9 over c
    float s = 0.f;
    for (int c = 0; c < 256; c++)
        s = fmaf(arow[c*9], c1w[c*64 + h], s);
    g_weff[(size_t)o*576 + tap*64 + h] = __float2half_rn(s);
    if (h == 0) {
        float sb = 0.f;
        for (int c = 0; c < 256; c++) sb = fmaf(arow[c*9], c1b[c], sb);
        if (tap == 4) sb += cAb[o];   // center tap always in-bounds
        g_bvec[tap*256 + o] = sb;
    }
}

// ---------------- fused pillar MLP (HMMA stage2, split-M) + pool + scatter --
__global__ void __launch_bounds__(256, 3) pillar_fused(
    const float* __restrict__ pillars, const int* __restrict__ nump,
    const int* __restrict__ indices, const float* __restrict__ w1,
    const float* __restrict__ b1, const float* __restrict__ b2,
    __half* __restrict__ a3)
{
    extern __shared__ char sm[];
    const int tid = threadIdx.x, lane = tid & 31, wid = tid >> 5;
    const uint32_t sb = smem_u32(sm);
    const int v0 = blockIdx.x * 8;

    float4* pts4   = (float4*)(sm + 40960);
    float*  pooled = (float*)(sm + 45056);
    float*  w1s    = (float*)(sm + 47104);
    float*  b1s    = (float*)(sm + 48128);
    float*  b2s    = (float*)(sm + 48384);
    float*  maskf  = (float*)(sm + 48640);
    int*    sxy    = (int*)(sm + 48672);

    w1s[tid] = w1[tid];
    if (tid < 64) { b1s[tid] = b1[tid]; b2s[tid] = b2[tid]; }
    if (tid < 8) {
        int v = v0 + tid;
        maskf[tid] = (nump[v] > 0) ? 1.f : 0.f;
        int xv = indices[2*v], yv = indices[2*v + 1];
        sxy[tid] = ((unsigned)xv < XDIM && (unsigned)yv < YDIM) ? xv*YDIM + yv : -1;
    }
    pts4[tid] = *(const float4*)(pillars + (size_t)v0*128 + tid*4);
    {
        const uint4* w2g = (const uint4*)g_w2h;
        #pragma unroll
        for (int i = 0; i < 2; i++) {
            int idx = tid*2 + i;
            int g = idx >> 3, grp = idx & 7;
            uint32_t off = 32768u + (uint32_t)((g*128 + grp*16) ^ ((g & 7) << 4));
            *(uint4*)(sm + off) = w2g[idx];
        }
    }
    __syncthreads();

    // ---- stage A: h1 = relu(x @ w1^T + b1) ----
    {
        float4 x = pts4[tid];
        float m = maskf[tid >> 5];
        x.x *= m; x.y *= m; x.z *= m; x.w *= m;
        const int phase = (tid >> 3) & 7;
        #pragma unroll
        for (int g8 = 0; g8 < 8; g8++) {
            int grp = (g8 + phase) & 7;
            uint32_t pk[4];
            #pragma unroll
            for (int u = 0; u < 4; u++) {
                int t0 = grp*8 + u*2;
                float4 wa = *(float4*)&w1s[t0*4];
                float4 wb = *(float4*)&w1s[t0*4 + 4];
                float h0 = fmaf(wa.x, x.x, fmaf(wa.y, x.y, fmaf(wa.z, x.z, fmaf(wa.w, x.w, b1s[t0]))));
                float h1v = fmaf(wb.x, x.x, fmaf(wb.y, x.y, fmaf(wb.z, x.z, fmaf(wb.w, x.w, b1s[t0+1]))));
                __half2 hh = __floats2half2_rn(fmaxf(h0, 0.f), fmaxf(h1v, 0.f));
                pk[u] = *(uint32_t*)&hh;
            }
            uint32_t off = (uint32_t)((tid*128 + grp*16) ^ ((tid & 7) << 4));
            *(uint4*)(sm + off) = make_uint4(pk[0], pk[1], pk[2], pk[3]);
        }
    }
    __syncthreads();

    // ---- stage B: per-warp pillar GEMM, split over M halves (regs diet) ----
    const int a_row = wid*32 + (lane & 15);
    const int a_kb  = (lane >> 4) * 16;
    const int b_row = ((lane & 16) >> 1) + (lane & 7);
    const int b_kb  = (lane & 8) ? 16 : 0;

    float pool0[8], pool1[8];
    #pragma unroll
    for (int nt = 0; nt < 8; nt++) { pool0[nt] = 0.f; pool1[nt] = 0.f; }

    for (int mt = 0; mt < 2; mt++) {
        float acc[8][4];
        #pragma unroll
        for (int j = 0; j < 8; j++)
            #pragma unroll
            for (int k = 0; k < 4; k++) acc[j][k] = 0.f;

        #pragma unroll
        for (int ks = 0; ks < 4; ks++) {
            uint32_t af[4], bf[8][2];
            {
                uint32_t off = (a_row + mt*16)*128 + a_kb + ks*32;
                off ^= (off >> 3) & 0x70;
                LDSM_X4(af[0], af[1], af[2], af[3], sb + off);
            }
            #pragma unroll
            for (int pr = 0; pr < 4; pr++) {
                uint32_t off = (b_row + pr*16)*128 + b_kb + ks*32;
                off ^= (off >> 3) & 0x70;
                LDSM_X4(bf[pr*2][0], bf[pr*2][1], bf[pr*2+1][0], bf[pr*2+1][1], sb + 32768u + off);
            }
            #pragma unroll
            for (int nt = 0; nt < 8; nt++)
                MMA_F16(acc[nt], af, bf[nt]);
        }

        #pragma unroll
        for (int nt = 0; nt < 8; nt++) {
            const int col = nt*8 + (lane & 3)*2;
            const float bb0 = b2s[col], bb1 = b2s[col + 1];
            pool0[nt] += fmaxf(acc[nt][0] + bb0, 0.f) + fmaxf(acc[nt][2] + bb0, 0.f);
            pool1[nt] += fmaxf(acc[nt][1] + bb1, 0.f) + fmaxf(acc[nt][3] + bb1, 0.f);
        }
    }

    #pragma unroll
    for (int nt = 0; nt < 8; nt++) {
        const int col = nt*8 + (lane & 3)*2;
        float s0 = pool0[nt], s1 = pool1[nt];
        #pragma unroll
        for (int o = 4; o < 32; o <<= 1) {
            s0 += __shfl_xor_sync(0xffffffffu, s0, o);
            s1 += __shfl_xor_sync(0xffffffffu, s1, o);
        }
        if (lane < 4) {
            pooled[wid*64 + col]     = s0 * (1.f/32.f);
            pooled[wid*64 + col + 1] = s1 * (1.f/32.f);
        }
    }
    __syncthreads();

    // ---- scatter pooled (fp16, 64ch) into a3a ----
    {
        int p = tid >> 5, c2 = (tid & 31) * 2;
        int xy = sxy[p];
        if (xy >= 0) {
            __half2 hv = __floats2half2_rn(pooled[p*64 + c2], pooled[p*64 + c2 + 1]);
            *(__half2*)(a3 + (size_t)xy*HID + c2) = hv;
        }
    }
}

// ---------------- mma.sync 3x3 conv (FOLD: conv1 folded into convA) --------
template<bool FOLD>
__global__ void __launch_bounds__(256, 2) conv_mma(
    const __half* __restrict__ a3w, const __half* __restrict__ b3w,
    const float* __restrict__ bias, __half* __restrict__ out,
    float* __restrict__ sumb, float* __restrict__ sqb)
{
    extern __shared__ char sm[];
    const char* a3 = (const char*)a3w;
    const char* b3 = (const char*)b3w;
    const int tid = threadIdx.x, wid = tid >> 5, lane = tid & 31;
    const int wm = wid >> 2, wn = wid & 3;
    const uint32_t sb = smem_u32(sm);
    float* sbC = (float*)(sm + 98304);   // indexed by FULL channel 0..255
    float* sbL = (float*)(sm + 99328);
    float* sbH = (float*)(sm + 100352);

    const int xr = blockIdx.x >> 2;
    const int y0 = (blockIdx.x & 3) * 128;
    const int p0 = xr*512 + y0;
    const int o0 = blockIdx.y * 128;

    constexpr int NCHUNK = FOLD ? 9 : 36;
    constexpr int AROWB  = FOLD ? 128 : 512;
    constexpr int BROWB  = FOLD ? 1152 : 4608;

    if (FOLD) {
        float bc = 0.f, bl = 0.f, bh = 0.f;
        #pragma unroll
        for (int tap = 0; tap < 9; tap++) {
            int dx = tap/3 - 1, dy = tap % 3 - 1;
            float bv = bias[tap*256 + tid];
            if ((unsigned)(xr + dx) < XDIM) {
                bc += bv;
                if (dy >= 0) bl += bv;
                if (dy <= 0) bh += bv;
            }
        }
        sbC[tid] = bc; sbL[tid] = bl; sbH[tid] = bh;
    } else {
        sbC[tid] = bias[tid];
    }

    const int a_row = wm*64 + (lane & 15);
    const int a_kb  = (lane >> 4) * 16;
    const int b_row = wn*32 + ((lane & 16) >> 1) + (lane & 7);
    const int b_kb  = (lane & 8) ? 16 : 0;

    const int l_row = tid >> 3;
    const int l_j   = (tid & 7) * 16;

    float acc[4][4][4];
    #pragma unroll
    for (int i = 0; i < 4; i++)
        #pragma unroll
        for (int j = 0; j < 4; j++)
            #pragma unroll
            for (int k = 0; k < 4; k++) acc[i][j][k] = 0.f;

    auto load_chunk = [&](int c, int slot) {
        const int tap = FOLD ? c : (c >> 2);
        const int kc  = FOLD ? 0 : (c & 3);
        const int dx = tap/3 - 1, dyy = tap - (tap/3)*3 - 1;
        const int xx = xr + dx;
        const bool xok = (unsigned)xx < XDIM;
        const uint32_t abase = sb + slot*32768u;
        const uint32_t bbase = abase + 16384u;
        #pragma unroll
        for (int i = 0; i < 4; i++) {
            int row = l_row + i*32;
            int yy = y0 + row + dyy;
            bool ok = xok && ((unsigned)yy < YDIM);
            const char* src = ok ? (a3 + (size_t)(xx*512 + yy)*AROWB + kc*128 + l_j)
                                 : a3;
            uint32_t off = row*128 + l_j; off ^= (off >> 3) & 0x70;
            CP_ASYNC(abase + off, src, ok ? 16 : 0);
        }
        #pragma unroll
        for (int i = 0; i < 4; i++) {
            int row = l_row + i*32;
            const char* src = b3 + (size_t)(o0 + row)*BROWB + c*128 + l_j;
            uint32_t off = row*128 + l_j; off ^= (off >> 3) & 0x70;
            CP_ASYNC(bbase + off, src, 16);
        }
    };

    load_chunk(0, 0); CP_COMMIT();
    load_chunk(1, 1); CP_COMMIT();

    for (int c = 0; c < NCHUNK; c++) {
        if (c < NCHUNK - 1) CP_WAIT1(); else CP_WAIT0();
        __syncthreads();
        if (c + 2 < NCHUNK) { load_chunk(c + 2, (c + 2) % 3); CP_COMMIT(); }

        const uint32_t sa  = sb + (uint32_t)(c % 3)*32768u;
        const uint32_t sbm = sa + 16384u;
        #pragma unroll
        for (int ks = 0; ks < 4; ks++) {
            uint32_t af[4][4], bf[4][2];
            #pragma unroll
            for (int mt = 0; mt < 4; mt++) {
                uint32_t off = (a_row + mt*16)*128 + a_kb + ks*32;
                off ^= (off >> 3) & 0x70;
                LDSM_X4(af[mt][0], af[mt][1], af[mt][2], af[mt][3], sa + off);
            }
            #pragma unroll
            for (int pr = 0; pr < 2; pr++) {
                uint32_t off = (b_row + pr*16)*128 + b_kb + ks*32;
                off ^= (off >> 3) & 0x70;
                LDSM_X4(bf[pr*2][0], bf[pr*2][1], bf[pr*2+1][0], bf[pr*2+1][1], sbm + off);
            }
            #pragma unroll
            for (int mt = 0; mt < 4; mt++)
                #pragma unroll
                for (int nt = 0; nt < 4; nt++)
                    MMA_F16(acc[mt][nt], af[mt], bf[nt]);
        }
    }

    // epilogue: edge-aware bias (FOLD), fp16 HWC store, fp32 BN stats
    #pragma unroll
    for (int nt = 0; nt < 4; nt++) {
        const int col = o0 + wn*32 + nt*8 + (lane & 3)*2;
        const float m0 = sbC[col], m1 = sbC[col + 1];
        float s0 = 0.f, q0 = 0.f, s1 = 0.f, q1 = 0.f;
        #pragma unroll
        for (int mt = 0; mt < 4; mt++) {
            const int yoff = wm*64 + mt*16 + (lane >> 2);
            const int prow = p0 + yoff;
            float b0a = m0, b1a = m1, b0b = m0, b1b = m1;
            if (FOLD) {
                int y1 = y0 + yoff;
                if (y1 == 0)       { b0a = sbL[col]; b1a = sbL[col + 1]; }
                if (y1 + 8 == 511) { b0b = sbH[col]; b1b = sbH[col + 1]; }
            }
            float v00 = acc[mt][nt][0] + b0a;
            float v01 = acc[mt][nt][1] + b1a;
            float v10 = acc[mt][nt][2] + b0b;
            float v11 = acc[mt][nt][3] + b1b;
            __half2 h0 = __floats2half2_rn(v00, v01);
            __half2 h1 = __floats2half2_rn(v10, v11);
            *(__half2*)(out + (size_t)prow*CO + col)     = h0;
            *(__half2*)(out + (size_t)(prow+8)*CO + col) = h1;
            s0 += v00 + v10; q0 += v00*v00 + v10*v10;
            s1 += v01 + v11; q1 += v01*v01 + v11*v11;
        }
        #pragma unroll
        for (int o = 4; o < 32; o <<= 1) {
            s0 += __shfl_xor_sync(0xffffffffu, s0, o);
            q0 += __shfl_xor_sync(0xffffffffu, q0, o);
            s1 += __shfl_xor_sync(0xffffffffu, s1, o);
            q1 += __shfl_xor_sync(0xffffffffu, q1, o);
        }
        if (lane < 4) {
            atomicAdd(sumb + col, s0); atomicAdd(sqb + col, q0);
            atomicAdd(sumb + col + 1, s1); atomicAdd(sqb + col + 1, q1);
        }
    }
}

// ---------------- BN finalize ----------------
__global__ void bn_finalize(const float* __restrict__ gamma,
                            const float* __restrict__ beta, int which) {
    int c = threadIdx.x;
    const float inv_n = 1.f / (float)NPIX;
    float mean = g_stats[which*512 + c] * inv_n;
    float var  = g_stats[which*512 + 256 + c] * inv_n - mean*mean;
    float sc = gamma[c] * rsqrtf(var + 1e-5f);
    g_bn[which*512 + c] = sc;
    g_bn[which*512 + 256 + c] = fmaf(-mean, sc, beta[c]);
}

// ---------------- BN-A apply + relu + fp16 convert ----------------
__global__ void bn_convert(const __half* __restrict__ in, __half* __restrict__ a3) {
    __shared__ float sc[256], sh[256];
    if (threadIdx.x < 256) {
        sc[threadIdx.x] = g_bn[threadIdx.x];
        sh[threadIdx.x] = g_bn[256 + threadIdx.x];
    }
    __syncthreads();
    const uint2* in4 = (const uint2*)in;
    const int total4 = NPIX * 64;
    for (int i = blockIdx.x*blockDim.x + threadIdx.x; i < total4; i += gridDim.x*blockDim.x) {
        uint2 raw = in4[i];
        __half2 p0 = *(__half2*)&raw.x;
        __half2 p1 = *(__half2*)&raw.y;
        int c = (i & 63) * 4;
        float f[4] = { __low2float(p0), __high2float(p0), __low2float(p1), __high2float(p1) };
        __half h[4];
        #pragma unroll
        for (int cc = 0; cc < 4; cc++)
            h[cc] = __float2half_rn(fmaxf(fmaf(f[cc], sc[c+cc], sh[c+cc]), 0.f));
        uint2 pk = make_uint2(
            ((uint32_t)__half_as_ushort(h[0])) | ((uint32_t)__half_as_ushort(h[1]) << 16),
            ((uint32_t)__half_as_ushort(h[2])) | ((uint32_t)__half_as_ushort(h[3]) << 16));
        ((uint2*)a3)[i] = pk;
    }
}

// ---------------- BN-B apply + relu + HWC->NCHW ----------------
__global__ void __launch_bounds__(256) bn_apply_nchw(const __half* __restrict__ in,
                                                     float* __restrict__ out) {
    __shared__ float s[32*257];
    const int tid = threadIdx.x;
    const float sc = g_bn[512 + tid];
    const float sh = g_bn[768 + tid];
    const int xy0 = blockIdx.x * 32;
    #pragma unroll
    for (int m = 0; m < 32; m++) {
        float v = __half2float(in[(size_t)(xy0 + m)*CO + tid]);
        s[m*257 + tid] = fmaxf(fmaf(v, sc, sh), 0.f);
    }
    __syncthreads();
    #pragma unroll
    for (int m = 0; m < 32; m++) {
        int o = m*8 + (tid >> 5);
        int xyl = tid & 31;
        out[(size_t)o*NPIX + xy0 + xyl] = s[xyl*257 + o];
    }
}

// ---------------- launch ----------------
extern "C" void kernel_launch(void* const* d_in, const int* in_sizes, int n_in,
                              void* d_out, int out_size) {
    const float* pillars = (const float*)d_in[0];
    const int*   nump    = (const int*)d_in[1];
    const int*   indices = (const int*)d_in[2];
    const float* w1   = (const float*)d_in[3];
    const float* b1   = (const float*)d_in[4];
    const float* w2   = (const float*)d_in[5];
    const float* b2   = (const float*)d_in[6];
    const float* c1w  = (const float*)d_in[7];
    const float* c1b  = (const float*)d_in[8];
    const float* cAw  = (const float*)d_in[9];
    const float* cAb  = (const float*)d_in[10];
    const float* bnAg = (const float*)d_in[11];
    const float* bnAb = (const float*)d_in[12];
    const float* cBw  = (const float*)d_in[13];
    const float* cBb  = (const float*)d_in[14];
    const float* bnBg = (const float*)d_in[15];
    const float* bnBb = (const float*)d_in[16];
    float* out = (float*)d_out;

    float *p_stats, *p_bvec;
    __half *p_h16, *p_a3a, *p_a3b, *p_weff, *p_bB;
    cudaGetSymbolAddress((void**)&p_h16,   g_h16);
    cudaGetSymbolAddress((void**)&p_stats, g_stats);
    cudaGetSymbolAddress((void**)&p_bvec,  g_bvec);
    cudaGetSymbolAddress((void**)&p_a3a,   g_a3a);
    cudaGetSymbolAddress((void**)&p_a3b,   g_a3b);
    cudaGetSymbolAddress((void**)&p_weff,  g_weff);
    cudaGetSymbolAddress((void**)&p_bB,    g_bB);

    static bool attr_done = false;
    if (!attr_done) {
        cudaFuncSetAttribute(conv_mma<true>,  cudaFuncAttributeMaxDynamicSharedMemorySize, 101376);
        cudaFuncSetAttribute(conv_mma<false>, cudaFuncAttributeMaxDynamicSharedMemorySize, 101376);
        attr_done = true;
    }

    zero_kernel<<<2048, 256>>>();
    prep_weights<<<1200, 256>>>(w2, cBw);
    prep_weff<<<CO*9, 64>>>(cAw, c1w, c1b, cAb);
    pillar_fused<<<VNUM/8, 256, 49152>>>(pillars, nump, indices, w1, b1, b2, p_a3a);

    dim3 cgrid(2048, 2);
    // convA (folded, K=576): a3a(64ch) -> h16 + stats
    conv_mma<true><<<cgrid, 256, 101376>>>(p_a3a, p_weff, p_bvec, p_h16, p_stats, p_stats + 256);
    bn_finalize<<<1, 256>>>(bnAg, bnAb, 0);

    bn_convert<<<4096, 256>>>(p_h16, p_a3b);

    // convB (K=2304): a3b -> h16 + stats
    conv_mma<false><<<cgrid, 256, 101376>>>(p_a3b, p_bB, cBb, p_h16, p_stats + 512, p_stats + 768);
    bn_finalize<<<1, 256>>>(bnBg, bnBb, 1);

    bn_apply_nchw<<<NPIX/32, 256>>>(p_h16, out);
}

// round 14
// speedup vs baseline: 2.4332x; 1.0467x over previous
#include <cuda_runtime.h>
#include <cuda_bf16.h>
#include <cuda_fp16.h>
#include <cstdint>

#define XDIM 512
#define YDIM 512
#define NPIX (XDIM*YDIM)      // 262144
#define VNUM 150000
#define HID 64
#define CO 256
#define KEFF 2304             // convB: 9 taps * 256 ch
#define KROW 256              // convB input row (halves)

// ---------------- scratch ----------------
__device__ __align__(256) __half g_h16[(size_t)NPIX*CO];   // pre-BN conv out (reused A/B)
__device__ __align__(256) __half g_a3a[(size_t)NPIX*HID];  // pooled BEV, 64ch fp16 (32MB)
__device__ __align__(256) __half g_a3b[(size_t)NPIX*KROW]; // convB input 256ch fp16
__device__ __align__(256) __half g_w2h[HID*HID];           // w2 fp16 [g][h]
__device__ __align__(256) __half g_weff[(size_t)CO*576];   // folded convA: [o][tap*64+h]
__device__ __align__(256) float g_bvec[9*CO];              // per-tap folded bias [tap][o]
__device__ __align__(256) __half g_bB[(size_t)CO*KEFF];    // convB weights [o][tap*256+c]
__device__ __align__(256) float g_stats[4*CO];
__device__ __align__(256) float g_bn[4*CO];

__device__ __forceinline__ uint32_t smem_u32(const void* p) {
    uint32_t a;
    asm("{ .reg .u64 t; cvta.to.shared.u64 t, %1; cvt.u32.u64 %0, t; }" : "=r"(a) : "l"(p));
    return a;
}

#define LDSM_X4(r0,r1,r2,r3,addr) \
    asm volatile("ldmatrix.sync.aligned.m8n8.x4.shared.b16 {%0,%1,%2,%3}, [%4];" \
        : "=r"(r0),"=r"(r1),"=r"(r2),"=r"(r3) : "r"(addr))
#define MMA_F16(d, a, b) \
    asm volatile("mma.sync.aligned.m16n8k16.row.col.f32.f16.f16.f32 " \
        "{%0,%1,%2,%3},{%4,%5,%6,%7},{%8,%9},{%0,%1,%2,%3};" \
        : "+f"((d)[0]),"+f"((d)[1]),"+f"((d)[2]),"+f"((d)[3]) \
        : "r"((a)[0]),"r"((a)[1]),"r"((a)[2]),"r"((a)[3]),"r"((b)[0]),"r"((b)[1]))
#define CP_ASYNC(dst, src, sz) \
    asm volatile("cp.async.cg.shared.global [%0], [%1], 16, %2;" \
        :: "r"(dst), "l"(src), "r"(sz))
#define CP_COMMIT() asm volatile("cp.async.commit_group;")
#define CP_WAIT1()  asm volatile("cp.async.wait_group 1;")
#define CP_WAIT0()  asm volatile("cp.async.wait_group 0;")

// ---------------- zero stats + zero a3a ----------------
__global__ void zero_kernel() {
    uint4* p = (uint4*)g_a3a;
    const int n16 = NPIX*HID*2/16;      // 2M uint4
    uint4 z = make_uint4(0,0,0,0);
    for (int i = blockIdx.x*blockDim.x + threadIdx.x; i < n16; i += gridDim.x*blockDim.x)
        p[i] = z;
    if (blockIdx.x == 0)
        for (int i = threadIdx.x; i < 4*CO; i += blockDim.x) g_stats[i] = 0.f;
}

// ---------------- weight prep: w2 fp16 + convB fp16 ----------------
__global__ void prep_weights(const float* __restrict__ w2,
                             const float* __restrict__ cBw) {
    const int totalw2 = HID*HID;      // 4096
    const int totalc = CO*CO*9;       // 589824
    for (int i = blockIdx.x*blockDim.x + threadIdx.x; i < totalw2 + totalc;
         i += gridDim.x*blockDim.x) {
        if (i < totalw2) {
            g_w2h[i] = __float2half_rn(w2[i]);
        } else {
            int j = i - totalw2;
            int o = j / 2304, k = j % 2304;
            int c = k / 9, tap = k % 9;
            g_bB[(size_t)o*KEFF + tap*KROW + c] = __float2half_rn(cBw[(size_t)o*2304 + c*9 + tap]);
        }
    }
}

// ---------------- fold conv1 into convA: weff + bvec (cAb folded into tap 4) -
__global__ void __launch_bounds__(64) prep_weff(
    const float* __restrict__ cAw, const float* __restrict__ c1w,
    const float* __restrict__ c1b, const float* __restrict__ cAb) {
    const int o = blockIdx.x / 9, tap = blockIdx.x % 9;
    const int h = threadIdx.x;
    const float* arow = cAw + (size_t)o*2304 + tap;   // stride 9 over c
    float s = 0.f;
    for (int c = 0; c < 256; c++)
        s = fmaf(arow[c*9], c1w[c*64 + h], s);
    g_weff[(size_t)o*576 + tap*64 + h] = __float2half_rn(s);
    if (h == 0) {
        float sb = 0.f;
        for (int c = 0; c < 256; c++) sb = fmaf(arow[c*9], c1b[c], sb);
        if (tap == 4) sb += cAb[o];   // center tap always in-bounds
        g_bvec[tap*256 + o] = sb;
    }
}

// ---------------- fused pillar MLP (HMMA stage2, split-M) + pool + scatter --
// stage A: thread = channel-pair (c2), warp = pillar; w1 in registers,
// pts broadcast LDS, one STS.32 per point. h1 layout identical to R13.
__global__ void __launch_bounds__(256, 3) pillar_fused(
    const float* __restrict__ pillars, const int* __restrict__ nump,
    const int* __restrict__ indices, const float* __restrict__ w1,
    const float* __restrict__ b1, const float* __restrict__ b2,
    __half* __restrict__ a3)
{
    extern __shared__ char sm[];
    const int tid = threadIdx.x, lane = tid & 31, wid = tid >> 5;
    const uint32_t sb = smem_u32(sm);
    const int v0 = blockIdx.x * 8;

    float4* pts4   = (float4*)(sm + 40960);
    float*  pooled = (float*)(sm + 45056);
    float*  b2s    = (float*)(sm + 48384);
    float*  maskf  = (float*)(sm + 48640);
    int*    sxy    = (int*)(sm + 48672);

    // per-thread w1 rows (channels lane*2, lane*2+1) in registers
    const float4 w1a = *(const float4*)(w1 + (lane*2)*4);
    const float4 w1b = *(const float4*)(w1 + (lane*2+1)*4);
    const float b1a = b1[lane*2], b1b = b1[lane*2+1];

    if (tid < 64) b2s[tid] = b2[tid];
    if (tid < 8) {
        int v = v0 + tid;
        maskf[tid] = (nump[v] > 0) ? 1.f : 0.f;
        int xv = indices[2*v], yv = indices[2*v + 1];
        sxy[tid] = ((unsigned)xv < XDIM && (unsigned)yv < YDIM) ? xv*YDIM + yv : -1;
    }
    pts4[tid] = *(const float4*)(pillars + (size_t)v0*128 + tid*4);
    {
        const uint4* w2g = (const uint4*)g_w2h;
        #pragma unroll
        for (int i = 0; i < 2; i++) {
            int idx = tid*2 + i;
            int g = idx >> 3, grp = idx & 7;
            uint32_t off = 32768u + (uint32_t)((g*128 + grp*16) ^ ((g & 7) << 4));
            *(uint4*)(sm + off) = w2g[idx];
        }
    }
    __syncthreads();

    // ---- stage A: h1 = relu(x @ w1^T + b1); warp wid = pillar wid ----
    {
        const float m = maskf[wid];
        const uint32_t cb = lane*4;       // byte col of this channel pair
        #pragma unroll 8
        for (int p = 0; p < 32; p++) {
            float4 x = pts4[wid*32 + p];  // warp-uniform broadcast
            x.x *= m; x.y *= m; x.z *= m; x.w *= m;
            float h0 = fmaf(w1a.x, x.x, fmaf(w1a.y, x.y, fmaf(w1a.z, x.z, fmaf(w1a.w, x.w, b1a))));
            float h1v = fmaf(w1b.x, x.x, fmaf(w1b.y, x.y, fmaf(w1b.z, x.z, fmaf(w1b.w, x.w, b1b))));
            __half2 hh = __floats2half2_rn(fmaxf(h0, 0.f), fmaxf(h1v, 0.f));
            const int row = wid*32 + p;
            uint32_t off = (uint32_t)row*128u + (cb ^ (uint32_t)((row & 7) << 4));
            *(uint32_t*)(sm + off) = *(uint32_t*)&hh;
        }
    }
    __syncthreads();

    // ---- stage B: per-warp pillar GEMM, split over M halves ----
    const int a_row = wid*32 + (lane & 15);
    const int a_kb  = (lane >> 4) * 16;
    const int b_row = ((lane & 16) >> 1) + (lane & 7);
    const int b_kb  = (lane & 8) ? 16 : 0;

    float pool0[8], pool1[8];
    #pragma unroll
    for (int nt = 0; nt < 8; nt++) { pool0[nt] = 0.f; pool1[nt] = 0.f; }

    for (int mt = 0; mt < 2; mt++) {
        float acc[8][4];
        #pragma unroll
        for (int j = 0; j < 8; j++)
            #pragma unroll
            for (int k = 0; k < 4; k++) acc[j][k] = 0.f;

        #pragma unroll
        for (int ks = 0; ks < 4; ks++) {
            uint32_t af[4], bf[8][2];
            {
                uint32_t off = (a_row + mt*16)*128 + a_kb + ks*32;
                off ^= (off >> 3) & 0x70;
                LDSM_X4(af[0], af[1], af[2], af[3], sb + off);
            }
            #pragma unroll
            for (int pr = 0; pr < 4; pr++) {
                uint32_t off = (b_row + pr*16)*128 + b_kb + ks*32;
                off ^= (off >> 3) & 0x70;
                LDSM_X4(bf[pr*2][0], bf[pr*2][1], bf[pr*2+1][0], bf[pr*2+1][1], sb + 32768u + off);
            }
            #pragma unroll
            for (int nt = 0; nt < 8; nt++)
                MMA_F16(acc[nt], af, bf[nt]);
        }

        #pragma unroll
        for (int nt = 0; nt < 8; nt++) {
            const int col = nt*8 + (lane & 3)*2;
            const float bb0 = b2s[col], bb1 = b2s[col + 1];
            pool0[nt] += fmaxf(acc[nt][0] + bb0, 0.f) + fmaxf(acc[nt][2] + bb0, 0.f);
            pool1[nt] += fmaxf(acc[nt][1] + bb1, 0.f) + fmaxf(acc[nt][3] + bb1, 0.f);
        }
    }

    #pragma unroll
    for (int nt = 0; nt < 8; nt++) {
        const int col = nt*8 + (lane & 3)*2;
        float s0 = pool0[nt], s1 = pool1[nt];
        #pragma unroll
        for (int o = 4; o < 32; o <<= 1) {
            s0 += __shfl_xor_sync(0xffffffffu, s0, o);
            s1 += __shfl_xor_sync(0xffffffffu, s1, o);
        }
        if (lane < 4) {
            pooled[wid*64 + col]     = s0 * (1.f/32.f);
            pooled[wid*64 + col + 1] = s1 * (1.f/32.f);
        }
    }
    __syncthreads();

    // ---- scatter pooled (fp16, 64ch) into a3a ----
    {
        int p = tid >> 5, c2 = (tid & 31) * 2;
        int xy = sxy[p];
        if (xy >= 0) {
            __half2 hv = __floats2half2_rn(pooled[p*64 + c2], pooled[p*64 + c2 + 1]);
            *(__half2*)(a3 + (size_t)xy*HID + c2) = hv;
        }
    }
}

// ---------------- mma.sync 3x3 conv (FOLD: conv1 folded into convA) --------
template<bool FOLD>
__global__ void __launch_bounds__(256, 2) conv_mma(
    const __half* __restrict__ a3w, const __half* __restrict__ b3w,
    const float* __restrict__ bias, __half* __restrict__ out,
    float* __restrict__ sumb, float* __restrict__ sqb)
{
    extern __shared__ char sm[];
    const char* a3 = (const char*)a3w;
    const char* b3 = (const char*)b3w;
    const int tid = threadIdx.x, wid = tid >> 5, lane = tid & 31;
    const int wm = wid >> 2, wn = wid & 3;
    const uint32_t sb = smem_u32(sm);
    float* sbC = (float*)(sm + 98304);   // indexed by FULL channel 0..255
    float* sbL = (float*)(sm + 99328);
    float* sbH = (float*)(sm + 100352);

    const int xr = blockIdx.x >> 2;
    const int y0 = (blockIdx.x & 3) * 128;
    const int p0 = xr*512 + y0;
    const int o0 = blockIdx.y * 128;

    constexpr int NCHUNK = FOLD ? 9 : 36;
    constexpr int AROWB  = FOLD ? 128 : 512;
    constexpr int BROWB  = FOLD ? 1152 : 4608;

    if (FOLD) {
        float bc = 0.f, bl = 0.f, bh = 0.f;
        #pragma unroll
        for (int tap = 0; tap < 9; tap++) {
            int dx = tap/3 - 1, dy = tap % 3 - 1;
            float bv = bias[tap*256 + tid];
            if ((unsigned)(xr + dx) < XDIM) {
                bc += bv;
                if (dy >= 0) bl += bv;
                if (dy <= 0) bh += bv;
            }
        }
        sbC[tid] = bc; sbL[tid] = bl; sbH[tid] = bh;
    } else {
        sbC[tid] = bias[tid];
    }

    const int a_row = wm*64 + (lane & 15);
    const int a_kb  = (lane >> 4) * 16;
    const int b_row = wn*32 + ((lane & 16) >> 1) + (lane & 7);
    const int b_kb  = (lane & 8) ? 16 : 0;

    const int l_row = tid >> 3;
    const int l_j   = (tid & 7) * 16;

    float acc[4][4][4];
    #pragma unroll
    for (int i = 0; i < 4; i++)
        #pragma unroll
        for (int j = 0; j < 4; j++)
            #pragma unroll
            for (int k = 0; k < 4; k++) acc[i][j][k] = 0.f;

    auto load_chunk = [&](int c, int slot) {
        const int tap = FOLD ? c : (c >> 2);
        const int kc  = FOLD ? 0 : (c & 3);
        const int dx = tap/3 - 1, dyy = tap - (tap/3)*3 - 1;
        const int xx = xr + dx;
        const bool xok = (unsigned)xx < XDIM;
        const uint32_t abase = sb + slot*32768u;
        const uint32_t bbase = abase + 16384u;
        #pragma unroll
        for (int i = 0; i < 4; i++) {
            int row = l_row + i*32;
            int yy = y0 + row + dyy;
            bool ok = xok && ((unsigned)yy < YDIM);
            const char* src = ok ? (a3 + (size_t)(xx*512 + yy)*AROWB + kc*128 + l_j)
                                 : a3;
            uint32_t off = row*128 + l_j; off ^= (off >> 3) & 0x70;
            CP_ASYNC(abase + off, src, ok ? 16 : 0);
        }
        #pragma unroll
        for (int i = 0; i < 4; i++) {
            int row = l_row + i*32;
            const char* src = b3 + (size_t)(o0 + row)*BROWB + c*128 + l_j;
            uint32_t off = row*128 + l_j; off ^= (off >> 3) & 0x70;
            CP_ASYNC(bbase + off, src, 16);
        }
    };

    load_chunk(0, 0); CP_COMMIT();
    load_chunk(1, 1); CP_COMMIT();

    for (int c = 0; c < NCHUNK; c++) {
        if (c < NCHUNK - 1) CP_WAIT1(); else CP_WAIT0();
        __syncthreads();
        if (c + 2 < NCHUNK) { load_chunk(c + 2, (c + 2) % 3); CP_COMMIT(); }

        const uint32_t sa  = sb + (uint32_t)(c % 3)*32768u;
        const uint32_t sbm = sa + 16384u;
        #pragma unroll
        for (int ks = 0; ks < 4; ks++) {
            uint32_t af[4][4], bf[4][2];
            #pragma unroll
            for (int mt = 0; mt < 4; mt++) {
                uint32_t off = (a_row + mt*16)*128 + a_kb + ks*32;
                off ^= (off >> 3) & 0x70;
                LDSM_X4(af[mt][0], af[mt][1], af[mt][2], af[mt][3], sa + off);
            }
            #pragma unroll
            for (int pr = 0; pr < 2; pr++) {
                uint32_t off = (b_row + pr*16)*128 + b_kb + ks*32;
                off ^= (off >> 3) & 0x70;
                LDSM_X4(bf[pr*2][0], bf[pr*2][1], bf[pr*2+1][0], bf[pr*2+1][1], sbm + off);
            }
            #pragma unroll
            for (int mt = 0; mt < 4; mt++)
                #pragma unroll
                for (int nt = 0; nt < 4; nt++)
                    MMA_F16(acc[mt][nt], af[mt], bf[nt]);
        }
    }

    // epilogue: edge-aware bias (FOLD), fp16 HWC store, fp32 BN stats
    #pragma unroll
    for (int nt = 0; nt < 4; nt++) {
        const int col = o0 + wn*32 + nt*8 + (lane & 3)*2;
        const float m0 = sbC[col], m1 = sbC[col + 1];
        float s0 = 0.f, q0 = 0.f, s1 = 0.f, q1 = 0.f;
        #pragma unroll
        for (int mt = 0; mt < 4; mt++) {
            const int yoff = wm*64 + mt*16 + (lane >> 2);
            const int prow = p0 + yoff;
            float b0a = m0, b1a = m1, b0b = m0, b1b = m1;
            if (FOLD) {
                int y1 = y0 + yoff;
                if (y1 == 0)       { b0a = sbL[col]; b1a = sbL[col + 1]; }
                if (y1 + 8 == 511) { b0b = sbH[col]; b1b = sbH[col + 1]; }
            }
            float v00 = acc[mt][nt][0] + b0a;
            float v01 = acc[mt][nt][1] + b1a;
            float v10 = acc[mt][nt][2] + b0b;
            float v11 = acc[mt][nt][3] + b1b;
            __half2 h0 = __floats2half2_rn(v00, v01);
            __half2 h1 = __floats2half2_rn(v10, v11);
            *(__half2*)(out + (size_t)prow*CO + col)     = h0;
            *(__half2*)(out + (size_t)(prow+8)*CO + col) = h1;
            s0 += v00 + v10; q0 += v00*v00 + v10*v10;
            s1 += v01 + v11; q1 += v01*v01 + v11*v11;
        }
        #pragma unroll
        for (int o = 4; o < 32; o <<= 1) {
            s0 += __shfl_xor_sync(0xffffffffu, s0, o);
            q0 += __shfl_xor_sync(0xffffffffu, q0, o);
            s1 += __shfl_xor_sync(0xffffffffu, s1, o);
            q1 += __shfl_xor_sync(0xffffffffu, q1, o);
        }
        if (lane < 4) {
            atomicAdd(sumb + col, s0); atomicAdd(sqb + col, q0);
            atomicAdd(sumb + col + 1, s1); atomicAdd(sqb + col + 1, q1);
        }
    }
}

// ---------------- BN finalize ----------------
__global__ void bn_finalize(const float* __restrict__ gamma,
                            const float* __restrict__ beta, int which) {
    int c = threadIdx.x;
    const float inv_n = 1.f / (float)NPIX;
    float mean = g_stats[which*512 + c] * inv_n;
    float var  = g_stats[which*512 + 256 + c] * inv_n - mean*mean;
    float sc = gamma[c] * rsqrtf(var + 1e-5f);
    g_bn[which*512 + c] = sc;
    g_bn[which*512 + 256 + c] = fmaf(-mean, sc, beta[c]);
}

// ---------------- BN-A apply + relu + fp16 convert ----------------
__global__ void bn_convert(const __half* __restrict__ in, __half* __restrict__ a3) {
    __shared__ float sc[256], sh[256];
    if (threadIdx.x < 256) {
        sc[threadIdx.x] = g_bn[threadIdx.x];
        sh[threadIdx.x] = g_bn[256 + threadIdx.x];
    }
    __syncthreads();
    const uint2* in4 = (const uint2*)in;
    const int total4 = NPIX * 64;
    for (int i = blockIdx.x*blockDim.x + threadIdx.x; i < total4; i += gridDim.x*blockDim.x) {
        uint2 raw = in4[i];
        __half2 p0 = *(__half2*)&raw.x;
        __half2 p1 = *(__half2*)&raw.y;
        int c = (i & 63) * 4;
        float f[4] = { __low2float(p0), __high2float(p0), __low2float(p1), __high2float(p1) };
        __half h[4];
        #pragma unroll
        for (int cc = 0; cc < 4; cc++)
            h[cc] = __float2half_rn(fmaxf(fmaf(f[cc], sc[c+cc], sh[c+cc]), 0.f));
        uint2 pk = make_uint2(
            ((uint32_t)__half_as_ushort(h[0])) | ((uint32_t)__half_as_ushort(h[1]) << 16),
            ((uint32_t)__half_as_ushort(h[2])) | ((uint32_t)__half_as_ushort(h[3]) << 16));
        ((uint2*)a3)[i] = pk;
    }
}

// ---------------- BN-B apply + relu + HWC->NCHW ----------------
__global__ void __launch_bounds__(256) bn_apply_nchw(const __half* __restrict__ in,
                                                     float* __restrict__ out) {
    __shared__ float s[32*257];
    const int tid = threadIdx.x;
    const float sc = g_bn[512 + tid];
    const float sh = g_bn[768 + tid];
    const int xy0 = blockIdx.x * 32;
    #pragma unroll
    for (int m = 0; m < 32; m++) {
        float v = __half2float(in[(size_t)(xy0 + m)*CO + tid]);
        s[m*257 + tid] = fmaxf(fmaf(v, sc, sh), 0.f);
    }
    __syncthreads();
    #pragma unroll
    for (int m = 0; m < 32; m++) {
        int o = m*8 + (tid >> 5);
        int xyl = tid & 31;
        out[(size_t)o*NPIX + xy0 + xyl] = s[xyl*257 + o];
    }
}

// ---------------- launch ----------------
extern "C" void kernel_launch(void* const* d_in, const int* in_sizes, int n_in,
                              void* d_out, int out_size) {
    const float* pillars = (const float*)d_in[0];
    const int*   nump    = (const int*)d_in[1];
    const int*   indices = (const int*)d_in[2];
    const float* w1   = (const float*)d_in[3];
    const float* b1   = (const float*)d_in[4];
    const float* w2   = (const float*)d_in[5];
    const float* b2   = (const float*)d_in[6];
    const float* c1w  = (const float*)d_in[7];
    const float* c1b  = (const float*)d_in[8];
    const float* cAw  = (const float*)d_in[9];
    const float* cAb  = (const float*)d_in[10];
    const float* bnAg = (const float*)d_in[11];
    const float* bnAb = (const float*)d_in[12];
    const float* cBw  = (const float*)d_in[13];
    const float* cBb  = (const float*)d_in[14];
    const float* bnBg = (const float*)d_in[15];
    const float* bnBb = (const float*)d_in[16];
    float* out = (float*)d_out;

    float *p_stats, *p_bvec;
    __half *p_h16, *p_a3a, *p_a3b, *p_weff, *p_bB;
    cudaGetSymbolAddress((void**)&p_h16,   g_h16);
    cudaGetSymbolAddress((void**)&p_stats, g_stats);
    cudaGetSymbolAddress((void**)&p_bvec,  g_bvec);
    cudaGetSymbolAddress((void**)&p_a3a,   g_a3a);
    cudaGetSymbolAddress((void**)&p_a3b,   g_a3b);
    cudaGetSymbolAddress((void**)&p_weff,  g_weff);
    cudaGetSymbolAddress((void**)&p_bB,    g_bB);

    static bool attr_done = false;
    if (!attr_done) {
        cudaFuncSetAttribute(conv_mma<true>,  cudaFuncAttributeMaxDynamicSharedMemorySize, 101376);
        cudaFuncSetAttribute(conv_mma<false>, cudaFuncAttributeMaxDynamicSharedMemorySize, 101376);
        attr_done = true;
    }

    zero_kernel<<<2048, 256>>>();
    prep_weights<<<1200, 256>>>(w2, cBw);
    prep_weff<<<CO*9, 64>>>(cAw, c1w, c1b, cAb);
    pillar_fused<<<VNUM/8, 256, 49152>>>(pillars, nump, indices, w1, b1, b2, p_a3a);

    dim3 cgrid(2048, 2);
    // convA (folded, K=576): a3a(64ch) -> h16 + stats
    conv_mma<true><<<cgrid, 256, 101376>>>(p_a3a, p_weff, p_bvec, p_h16, p_stats, p_stats + 256);
    bn_finalize<<<1, 256>>>(bnAg, bnAb, 0);

    bn_convert<<<4096, 256>>>(p_h16, p_a3b);

    // convB (K=2304): a3b -> h16 + stats
    conv_mma<false><<<cgrid, 256, 101376>>>(p_a3b, p_bB, cBb, p_h16, p_stats + 512, p_stats + 768);
    bn_finalize<<<1, 256>>>(bnBg, bnBb, 1);

    bn_apply_nchw<<<NPIX/32, 256>>>(p_h16, out);
}